// round 5
// baseline (speedup 1.0000x reference)
#include <cuda_runtime.h>
#include <cuda_bf16.h>
#include <math.h>

// ---------------- problem constants ----------------
#define NPTS    524288
#define GRID_D  300
#define NCOMP   36
#define SDF_DIM 256
#define OUT_CH  129      // 1 + APP_DIM
#define IN_CH   129      // 21 embed + 108 feat
#define IN_PAD  132      // padded to multiple of 4
#define OUT_PAD 132
#define BP      32       // points per block
#define NTHR    128
#define NBLK    (NPTS / BP)   // 16384

// smem (64-bit dup words): A_dup[32][132] + H_dup[32][257]
#define H_PITCH 257
#define SMEM_ULL  (BP * IN_PAD + BP * H_PITCH)   // 4224 + 8224 = 12448
#define SMEM_BYTES (SMEM_ULL * 8)                // 99,584 B

typedef unsigned long long ull;

// ---------------- scratch (device globals; no allocation allowed) ----------------
__device__ __align__(16) float g_planesT[3 * GRID_D * GRID_D * NCOMP]; // [p][y][x][c]
__device__ __align__(16) float g_linesT[3 * GRID_D * NCOMP];           // [p][z][c]
__device__ __align__(16) float g_w1T[IN_PAD * SDF_DIM];                // [k_new][j]
__device__ __align__(16) float g_w2T[SDF_DIM * OUT_PAD];               // [sigma][o]

// ---------------- f32x2 helpers ----------------
__device__ __forceinline__ void ffma2(ull& d, ull a, ull b) {
    asm("fma.rn.f32x2 %0, %1, %2, %0;" : "+l"(d) : "l"(a), "l"(b));
}
__device__ __forceinline__ ull dup2(float x) {
    ull r; asm("mov.b64 %0, {%1, %1};" : "=l"(r) : "f"(x)); return r;
}
__device__ __forceinline__ void unpk(ull v, float& lo, float& hi) {
    asm("mov.b64 {%0, %1}, %2;" : "=f"(lo), "=f"(hi) : "l"(v));
}

// ---------------- preprocess: plane transpose [3][36][300][300] -> [3][300][300][36] ----------------
__global__ void transpose_planes_kernel(const float* __restrict__ planes) {
    int b = blockIdx.x;
    int xt = b % 10;
    int rest = b / 10;
    int y = rest % GRID_D;
    int p = rest / GRID_D;
    int x0 = xt * 32;

    __shared__ float tile[NCOMP][33];

    for (int idx = threadIdx.x; idx < NCOMP * 32; idx += blockDim.x) {
        int c = idx >> 5;
        int xx = idx & 31;
        if (x0 + xx < GRID_D)
            tile[c][xx] = planes[((p * NCOMP + c) * GRID_D + y) * GRID_D + x0 + xx];
    }
    __syncthreads();
    for (int idx = threadIdx.x; idx < 32 * NCOMP; idx += blockDim.x) {
        int xx = idx / NCOMP;
        int c  = idx % NCOMP;
        if (x0 + xx < GRID_D)
            g_planesT[((p * GRID_D + y) * GRID_D + (x0 + xx)) * NCOMP + c] = tile[c][xx];
    }
}

// ---------------- preprocess: w1 (permute+transpose+pad), w2 (sigma-order+pad), lines transpose ----------------
// w1 new input-channel order: [feat(108) = orig 21..128, embed(21) = orig 0..20, pad(3)=0]
// w2 row order sigma: j(sigma) = pass*128 + lane*4 + c, sigma = c*64 + pass*32 + lane
__global__ void prep_small_kernel(const float* __restrict__ w1,
                                  const float* __restrict__ w2,
                                  const float* __restrict__ lines) {
    int i = blockIdx.x * blockDim.x + threadIdx.x;
    const int W1T_N = IN_PAD * SDF_DIM;     // 33792
    const int W2T_N = SDF_DIM * OUT_PAD;    // 33792
    const int LNT_N = 3 * GRID_D * NCOMP;   // 32400
    if (i < W1T_N) {
        int k = i >> 8;          // new channel index
        int j = i & 255;
        float v = 0.0f;
        if (k < IN_CH) {
            int orig = (k < 108) ? (21 + k) : (k - 108);
            v = w1[j * IN_CH + orig];
        }
        g_w1T[i] = v;
    } else if (i < W1T_N + W2T_N) {
        int t = i - W1T_N;
        int s = t / OUT_PAD;     // sigma
        int o = t % OUT_PAD;
        int c    = s >> 6;
        int pass = (s >> 5) & 1;
        int lane = s & 31;
        int j = pass * 128 + lane * 4 + c;
        g_w2T[t] = (o < OUT_CH) ? w2[o * SDF_DIM + j] : 0.0f;
    } else if (i < W1T_N + W2T_N + LNT_N) {
        int t = i - W1T_N - W2T_N;
        int c = t % NCOMP;
        int z = (t / NCOMP) % GRID_D;
        int p = t / (NCOMP * GRID_D);
        g_linesT[t] = lines[(p * NCOMP + c) * GRID_D + z];
    }
}

// ---------------- activation: softplus(100u)/100, branch-free stable form ----------------
__device__ __forceinline__ float actf(float u) {
    float t = 100.0f * u;
    return (fmaxf(t, 0.0f) + __logf(1.0f + __expf(-fabsf(t)))) * 0.01f;
}

// ---------------- fused main kernel ----------------
__global__ __launch_bounds__(NTHR, 2)
void tensosdf_main_kernel(const float* __restrict__ xyz,
                          const float* __restrict__ b1,
                          const float* __restrict__ b2,
                          float* __restrict__ out) {
    extern __shared__ ull sm_u[];
    ull* A_s = sm_u;                    // [32][132] dup pairs (a,a)
    ull* H_s = sm_u + BP * IN_PAD;      // [32][257] dup pairs (h,h)

    const int tid = threadIdx.x;
    const int pt0 = blockIdx.x * BP;

    // ---- Phase A: features + embedding into A_s (duplicated pairs) ----
    if (tid < 96) {
        // one (point, plane) task per thread: 32 pts x 3 planes
        int point = tid / 3;
        int p     = tid - point * 3;
        int gp = pt0 + point;
        float x = xyz[gp * 3 + 0];
        float y = xyz[gp * 3 + 1];
        float z = xyz[gp * 3 + 2];
        float sx, sy, sz;
        if (p == 0)      { sx = x; sy = y; sz = z; }
        else if (p == 1) { sx = x; sy = z; sz = y; }
        else             { sx = y; sy = z; sz = x; }

        const float HALF = 0.5f * (GRID_D - 1);
        float fx = (sx + 1.0f) * HALF;
        float fy = (sy + 1.0f) * HALF;
        float fz = (sz + 1.0f) * HALF;
        int x0 = min(max((int)floorf(fx), 0), GRID_D - 2);
        int y0 = min(max((int)floorf(fy), 0), GRID_D - 2);
        int z0 = min(max((int)floorf(fz), 0), GRID_D - 2);
        float tx = fx - (float)x0;
        float ty = fy - (float)y0;
        float tz = fz - (float)z0;

        float w00 = (1.0f - tx) * (1.0f - ty);
        float w01 = tx * (1.0f - ty);
        float w10 = (1.0f - tx) * ty;
        float w11 = tx * ty;

        const float4* base = (const float4*)(g_planesT + (size_t)((p * GRID_D + y0) * GRID_D + x0) * NCOMP);
        const float4* lb   = (const float4*)(g_linesT + (size_t)(p * GRID_D + z0) * NCOMP);
        ull* dst = A_s + point * IN_PAD + p * NCOMP;   // feat block at cols [p*36, p*36+36)
        #pragma unroll
        for (int cc = 0; cc < 9; cc++) {
            float4 v00 = base[cc];
            float4 v01 = base[9 + cc];
            float4 v10 = base[2700 + cc];
            float4 v11 = base[2709 + cc];
            float4 l0 = lb[cc];
            float4 l1 = lb[9 + cc];
            float rx = (v00.x * w00 + v01.x * w01 + v10.x * w10 + v11.x * w11) * (l0.x + (l1.x - l0.x) * tz);
            float ry = (v00.y * w00 + v01.y * w01 + v10.y * w10 + v11.y * w11) * (l0.y + (l1.y - l0.y) * tz);
            float rz = (v00.z * w00 + v01.z * w01 + v10.z * w10 + v11.z * w11) * (l0.z + (l1.z - l0.z) * tz);
            float rw = (v00.w * w00 + v01.w * w01 + v10.w * w10 + v11.w * w11) * (l0.w + (l1.w - l0.w) * tz);
            dst[cc * 4 + 0] = dup2(rx);
            dst[cc * 4 + 1] = dup2(ry);
            dst[cc * 4 + 2] = dup2(rz);
            dst[cc * 4 + 3] = dup2(rw);
        }
    } else {
        // embedding: one point per thread (32 threads -> 32 points)
        int point = tid - 96;
        int gp = pt0 + point;
        float v[3];
        v[0] = xyz[gp * 3 + 0];
        v[1] = xyz[gp * 3 + 1];
        v[2] = xyz[gp * 3 + 2];
        ull* dst = A_s + point * IN_PAD + 108;   // embed block at cols [108,129)
        dst[0] = dup2(v[0]); dst[1] = dup2(v[1]); dst[2] = dup2(v[2]);
        #pragma unroll
        for (int d = 0; d < 3; d++) {
            #pragma unroll
            for (int f = 0; f < 3; f++) {
                float s, c;
                sincosf(v[d] * (float)(1 << f), &s, &c);
                dst[3 + d * 3 + f]  = dup2(s);
                dst[12 + d * 3 + f] = dup2(c);
            }
        }
        dst[21] = 0ull; dst[22] = 0ull; dst[23] = 0ull;   // pad cols 129..131
    }
    __syncthreads();

    const int wid  = tid >> 5;
    const int lane = tid & 31;
    const int ib   = wid * 8;   // this warp's 8 points

    // ---- GEMM1: H = act(A @ w1T + b1), j-pairs per lane, 2 passes of 128 ----
    #pragma unroll 1
    for (int pass = 0; pass < 2; pass++) {
        const int j0 = pass * 128 + lane * 4;
        ulonglong2 bb = *(const ulonglong2*)(b1 + j0);
        ull acc0[8], acc1[8];
        #pragma unroll
        for (int i = 0; i < 8; i++) { acc0[i] = bb.x; acc1[i] = bb.y; }

        const ull* ab = A_s + ib * IN_PAD;
        const float* wb = g_w1T + j0;
        #pragma unroll 4
        for (int k = 0; k < IN_PAD; k++) {
            ulonglong2 w = *(const ulonglong2*)(wb + k * SDF_DIM);
            #pragma unroll
            for (int i = 0; i < 8; i++) {
                ull a = ab[i * IN_PAD + k];
                ffma2(acc0[i], a, w.x);
                ffma2(acc1[i], a, w.y);
            }
        }
        // activation + dup-store to H in sigma order: sigma = c*64 + pass*32 + lane
        const int colbase = pass * 32 + lane;
        #pragma unroll
        for (int i = 0; i < 8; i++) {
            float h0, h1, h2, h3;
            unpk(acc0[i], h0, h1);
            unpk(acc1[i], h2, h3);
            h0 = actf(h0); h1 = actf(h1); h2 = actf(h2); h3 = actf(h3);
            ull* hp = H_s + (ib + i) * H_PITCH;
            hp[colbase      ] = dup2(h0);   // c=0
            hp[colbase +  64] = dup2(h1);   // c=1
            hp[colbase + 128] = dup2(h2);   // c=2
            hp[colbase + 192] = dup2(h3);   // c=3
        }
    }
    __syncthreads();

    // ---- GEMM2: out = H @ w2T + b2 (o in [0,128) here; o=128 in cleanup) ----
    {
        const int o0 = lane * 4;
        ulonglong2 bb = *(const ulonglong2*)(b2 + o0);
        ull acc0[8], acc1[8];
        #pragma unroll
        for (int i = 0; i < 8; i++) { acc0[i] = bb.x; acc1[i] = bb.y; }

        const ull* hb = H_s + ib * H_PITCH;
        const float* wb = g_w2T + o0;
        #pragma unroll 4
        for (int s = 0; s < SDF_DIM; s++) {
            ulonglong2 w = *(const ulonglong2*)(wb + s * OUT_PAD);
            #pragma unroll
            for (int i = 0; i < 8; i++) {
                ull h = hb[i * H_PITCH + s];
                ffma2(acc0[i], h, w.x);
                ffma2(acc1[i], h, w.y);
            }
        }
        #pragma unroll
        for (int i = 0; i < 8; i++) {
            float r0, r1, r2, r3;
            unpk(acc0[i], r0, r1);
            unpk(acc1[i], r2, r3);
            float* op = out + (size_t)(pt0 + ib + i) * OUT_CH + o0;
            op[0] = r0; op[1] = r1; op[2] = r2; op[3] = r3;
        }
    }

    // ---- cleanup: output channel o = 128 (one thread per point) ----
    if (tid < BP) {
        float acc = b2[128];
        const float* hf = (const float*)(H_s + tid * H_PITCH);   // lo half of dup pair
        #pragma unroll 4
        for (int s = 0; s < SDF_DIM; s++) {
            acc += hf[2 * s] * g_w2T[s * OUT_PAD + 128];
        }
        out[(size_t)(pt0 + tid) * OUT_CH + 128] = acc;
    }
}

// ---------------- launch ----------------
extern "C" void kernel_launch(void* const* d_in, const int* in_sizes, int n_in,
                              void* d_out, int out_size) {
    const float* xyz    = (const float*)d_in[0];
    const float* planes = (const float*)d_in[1];
    const float* lines  = (const float*)d_in[2];
    const float* w1     = (const float*)d_in[3];
    const float* b1     = (const float*)d_in[4];
    const float* w2     = (const float*)d_in[5];
    const float* b2     = (const float*)d_in[6];
    float* out = (float*)d_out;

    cudaFuncSetAttribute(tensosdf_main_kernel,
                         cudaFuncAttributeMaxDynamicSharedMemorySize, SMEM_BYTES);

    transpose_planes_kernel<<<3 * GRID_D * 10, 256>>>(planes);

    const int prep_total = IN_PAD * SDF_DIM + SDF_DIM * OUT_PAD + 3 * GRID_D * NCOMP;
    prep_small_kernel<<<(prep_total + 255) / 256, 256>>>(w1, w2, lines);

    tensosdf_main_kernel<<<NBLK, NTHR, SMEM_BYTES>>>(xyz, b1, b2, out);
}

// round 6
// speedup vs baseline: 1.4996x; 1.4996x over previous
#include <cuda_runtime.h>
#include <cuda_bf16.h>
#include <math.h>

// ---------------- problem constants ----------------
#define NPTS    524288
#define GRID_D  300
#define NCOMP   36
#define SDF_DIM 256
#define OUT_CH  129      // 1 + APP_DIM
#define IN_CH   129      // 21 embed + 108 feat
#define IN_PAD  132      // padded to multiple of 4
#define OUT_PAD 132
#define BP      32       // points per block
#define NTHR    128
#define NBLK    (NPTS / BP)   // 16384

// smem (64-bit dup words): A_dup[32][132] + H_dup[32][257]
#define H_PITCH 257
#define SMEM_ULL  (BP * IN_PAD + BP * H_PITCH)   // 4224 + 8224 = 12448
#define SMEM_BYTES (SMEM_ULL * 8)                // 99,584 B

typedef unsigned long long ull;

// ---------------- scratch (device globals; no allocation allowed) ----------------
__device__ __align__(16) float g_planesT[3 * GRID_D * GRID_D * NCOMP]; // [p][y][x][c]
__device__ __align__(16) float g_linesT[3 * GRID_D * NCOMP];           // [p][z][c]
__device__ __align__(16) float g_w1T[IN_PAD * SDF_DIM];                // [k_new][j]
__device__ __align__(16) float g_w2T[SDF_DIM * OUT_PAD];               // [sigma][o]

// ---------------- f32x2 helpers ----------------
__device__ __forceinline__ void ffma2(ull& d, ull a, ull b) {
    asm("fma.rn.f32x2 %0, %1, %2, %0;" : "+l"(d) : "l"(a), "l"(b));
}
__device__ __forceinline__ ull dup2(float x) {
    ull r; asm("mov.b64 %0, {%1, %1};" : "=l"(r) : "f"(x)); return r;
}
__device__ __forceinline__ void unpk(ull v, float& lo, float& hi) {
    asm("mov.b64 {%0, %1}, %2;" : "=f"(lo), "=f"(hi) : "l"(v));
}

// ---------------- preprocess: plane transpose [3][36][300][300] -> [3][300][300][36] ----------------
__global__ void transpose_planes_kernel(const float* __restrict__ planes) {
    int b = blockIdx.x;
    int xt = b % 10;
    int rest = b / 10;
    int y = rest % GRID_D;
    int p = rest / GRID_D;
    int x0 = xt * 32;

    __shared__ float tile[NCOMP][33];

    for (int idx = threadIdx.x; idx < NCOMP * 32; idx += blockDim.x) {
        int c = idx >> 5;
        int xx = idx & 31;
        if (x0 + xx < GRID_D)
            tile[c][xx] = planes[((p * NCOMP + c) * GRID_D + y) * GRID_D + x0 + xx];
    }
    __syncthreads();
    for (int idx = threadIdx.x; idx < 32 * NCOMP; idx += blockDim.x) {
        int xx = idx / NCOMP;
        int c  = idx % NCOMP;
        if (x0 + xx < GRID_D)
            g_planesT[((p * GRID_D + y) * GRID_D + (x0 + xx)) * NCOMP + c] = tile[c][xx];
    }
}

// ---------------- preprocess: w1 (permute+transpose+pad), w2 (sigma-order+pad), lines transpose ----------------
// w1 new input-channel order: [feat(108) = orig 21..128, embed(21) = orig 0..20, pad(3)=0]
// w2 row order sigma: j(sigma) = pass*128 + lane*4 + c, sigma = c*64 + pass*32 + lane
__global__ void prep_small_kernel(const float* __restrict__ w1,
                                  const float* __restrict__ w2,
                                  const float* __restrict__ lines) {
    int i = blockIdx.x * blockDim.x + threadIdx.x;
    const int W1T_N = IN_PAD * SDF_DIM;     // 33792
    const int W2T_N = SDF_DIM * OUT_PAD;    // 33792
    const int LNT_N = 3 * GRID_D * NCOMP;   // 32400
    if (i < W1T_N) {
        int k = i >> 8;          // new channel index
        int j = i & 255;
        float v = 0.0f;
        if (k < IN_CH) {
            int orig = (k < 108) ? (21 + k) : (k - 108);
            v = w1[j * IN_CH + orig];
        }
        g_w1T[i] = v;
    } else if (i < W1T_N + W2T_N) {
        int t = i - W1T_N;
        int s = t / OUT_PAD;     // sigma
        int o = t % OUT_PAD;
        int c    = s >> 6;
        int pass = (s >> 5) & 1;
        int lane = s & 31;
        int j = pass * 128 + lane * 4 + c;
        g_w2T[t] = (o < OUT_CH) ? w2[o * SDF_DIM + j] : 0.0f;
    } else if (i < W1T_N + W2T_N + LNT_N) {
        int t = i - W1T_N - W2T_N;
        int c = t % NCOMP;
        int z = (t / NCOMP) % GRID_D;
        int p = t / (NCOMP * GRID_D);
        g_linesT[t] = lines[(p * NCOMP + c) * GRID_D + z];
    }
}

// ---------------- activation: softplus(100u)/100, branch-free stable form ----------------
__device__ __forceinline__ float actf(float u) {
    float t = 100.0f * u;
    return (fmaxf(t, 0.0f) + __logf(1.0f + __expf(-fabsf(t)))) * 0.01f;
}

// ---------------- fused main kernel ----------------
__global__ __launch_bounds__(NTHR, 2)
void tensosdf_main_kernel(const float* __restrict__ xyz,
                          const float* __restrict__ b1,
                          const float* __restrict__ b2,
                          float* __restrict__ out) {
    extern __shared__ ull sm_u[];
    ull* A_s = sm_u;                    // [32][132] dup pairs (a,a)
    ull* H_s = sm_u + BP * IN_PAD;      // [32][257] dup pairs (h,h)

    const int tid = threadIdx.x;
    const int pt0 = blockIdx.x * BP;

    // ---- Phase A: features + embedding into A_s (duplicated pairs) ----
    if (tid < 96) {
        // one (point, plane) task per thread: 32 pts x 3 planes
        int point = tid / 3;
        int p     = tid - point * 3;
        int gp = pt0 + point;
        float x = xyz[gp * 3 + 0];
        float y = xyz[gp * 3 + 1];
        float z = xyz[gp * 3 + 2];
        float sx, sy, sz;
        if (p == 0)      { sx = x; sy = y; sz = z; }
        else if (p == 1) { sx = x; sy = z; sz = y; }
        else             { sx = y; sy = z; sz = x; }

        const float HALF = 0.5f * (GRID_D - 1);
        float fx = (sx + 1.0f) * HALF;
        float fy = (sy + 1.0f) * HALF;
        float fz = (sz + 1.0f) * HALF;
        int x0 = min(max((int)floorf(fx), 0), GRID_D - 2);
        int y0 = min(max((int)floorf(fy), 0), GRID_D - 2);
        int z0 = min(max((int)floorf(fz), 0), GRID_D - 2);
        float tx = fx - (float)x0;
        float ty = fy - (float)y0;
        float tz = fz - (float)z0;

        float w00 = (1.0f - tx) * (1.0f - ty);
        float w01 = tx * (1.0f - ty);
        float w10 = (1.0f - tx) * ty;
        float w11 = tx * ty;

        const float4* base = (const float4*)(g_planesT + (size_t)((p * GRID_D + y0) * GRID_D + x0) * NCOMP);
        const float4* lb   = (const float4*)(g_linesT + (size_t)(p * GRID_D + z0) * NCOMP);
        ull* dst = A_s + point * IN_PAD + p * NCOMP;   // feat block at cols [p*36, p*36+36)
        #pragma unroll
        for (int cc = 0; cc < 9; cc++) {
            float4 v00 = base[cc];
            float4 v01 = base[9 + cc];
            float4 v10 = base[2700 + cc];
            float4 v11 = base[2709 + cc];
            float4 l0 = lb[cc];
            float4 l1 = lb[9 + cc];
            float rx = (v00.x * w00 + v01.x * w01 + v10.x * w10 + v11.x * w11) * (l0.x + (l1.x - l0.x) * tz);
            float ry = (v00.y * w00 + v01.y * w01 + v10.y * w10 + v11.y * w11) * (l0.y + (l1.y - l0.y) * tz);
            float rz = (v00.z * w00 + v01.z * w01 + v10.z * w10 + v11.z * w11) * (l0.z + (l1.z - l0.z) * tz);
            float rw = (v00.w * w00 + v01.w * w01 + v10.w * w10 + v11.w * w11) * (l0.w + (l1.w - l0.w) * tz);
            dst[cc * 4 + 0] = dup2(rx);
            dst[cc * 4 + 1] = dup2(ry);
            dst[cc * 4 + 2] = dup2(rz);
            dst[cc * 4 + 3] = dup2(rw);
        }
    } else {
        // embedding: one point per thread (32 threads -> 32 points)
        int point = tid - 96;
        int gp = pt0 + point;
        float v[3];
        v[0] = xyz[gp * 3 + 0];
        v[1] = xyz[gp * 3 + 1];
        v[2] = xyz[gp * 3 + 2];
        ull* dst = A_s + point * IN_PAD + 108;   // embed block at cols [108,129)
        dst[0] = dup2(v[0]); dst[1] = dup2(v[1]); dst[2] = dup2(v[2]);
        #pragma unroll
        for (int d = 0; d < 3; d++) {
            #pragma unroll
            for (int f = 0; f < 3; f++) {
                float s, c;
                sincosf(v[d] * (float)(1 << f), &s, &c);
                dst[3 + d * 3 + f]  = dup2(s);
                dst[12 + d * 3 + f] = dup2(c);
            }
        }
        dst[21] = 0ull; dst[22] = 0ull; dst[23] = 0ull;   // pad cols 129..131
    }
    __syncthreads();

    const int wid  = tid >> 5;
    const int lane = tid & 31;
    const int ib   = wid * 8;   // this warp's 8 points

    // ---- GEMM1: H = act(A @ w1T + b1), j-pairs per lane, 2 passes of 128 ----
    #pragma unroll 1
    for (int pass = 0; pass < 2; pass++) {
        const int j0 = pass * 128 + lane * 4;
        ulonglong2 bb = *(const ulonglong2*)(b1 + j0);
        ull acc0[8], acc1[8];
        #pragma unroll
        for (int i = 0; i < 8; i++) { acc0[i] = bb.x; acc1[i] = bb.y; }

        const ull* ab = A_s + ib * IN_PAD;
        const float* wb = g_w1T + j0;
        #pragma unroll 4
        for (int k = 0; k < IN_PAD; k++) {
            ulonglong2 w = *(const ulonglong2*)(wb + k * SDF_DIM);
            #pragma unroll
            for (int i = 0; i < 8; i++) {
                ull a = ab[i * IN_PAD + k];
                ffma2(acc0[i], a, w.x);
                ffma2(acc1[i], a, w.y);
            }
        }
        // activation + dup-store to H in sigma order: sigma = c*64 + pass*32 + lane
        const int colbase = pass * 32 + lane;
        #pragma unroll
        for (int i = 0; i < 8; i++) {
            float h0, h1, h2, h3;
            unpk(acc0[i], h0, h1);
            unpk(acc1[i], h2, h3);
            h0 = actf(h0); h1 = actf(h1); h2 = actf(h2); h3 = actf(h3);
            ull* hp = H_s + (ib + i) * H_PITCH;
            hp[colbase      ] = dup2(h0);   // c=0
            hp[colbase +  64] = dup2(h1);   // c=1
            hp[colbase + 128] = dup2(h2);   // c=2
            hp[colbase + 192] = dup2(h3);   // c=3
        }
    }
    __syncthreads();

    // ---- GEMM2: out = H @ w2T + b2 (o in [0,128) here; o=128 in cleanup) ----
    {
        const int o0 = lane * 4;
        ulonglong2 bb = *(const ulonglong2*)(b2 + o0);
        ull acc0[8], acc1[8];
        #pragma unroll
        for (int i = 0; i < 8; i++) { acc0[i] = bb.x; acc1[i] = bb.y; }

        const ull* hb = H_s + ib * H_PITCH;
        const float* wb = g_w2T + o0;
        #pragma unroll 4
        for (int s = 0; s < SDF_DIM; s++) {
            ulonglong2 w = *(const ulonglong2*)(wb + s * OUT_PAD);
            #pragma unroll
            for (int i = 0; i < 8; i++) {
                ull h = hb[i * H_PITCH + s];
                ffma2(acc0[i], h, w.x);
                ffma2(acc1[i], h, w.y);
            }
        }
        #pragma unroll
        for (int i = 0; i < 8; i++) {
            float r0, r1, r2, r3;
            unpk(acc0[i], r0, r1);
            unpk(acc1[i], r2, r3);
            float* op = out + (size_t)(pt0 + ib + i) * OUT_CH + o0;
            op[0] = r0; op[1] = r1; op[2] = r2; op[3] = r3;
        }
    }

    // ---- cleanup: output channel o = 128 (one thread per point) ----
    if (tid < BP) {
        float acc = b2[128];
        const float* hf = (const float*)(H_s + tid * H_PITCH);   // lo half of dup pair
        #pragma unroll 4
        for (int s = 0; s < SDF_DIM; s++) {
            acc += hf[2 * s] * g_w2T[s * OUT_PAD + 128];
        }
        out[(size_t)(pt0 + tid) * OUT_CH + 128] = acc;
    }
}

// ---------------- launch ----------------
extern "C" void kernel_launch(void* const* d_in, const int* in_sizes, int n_in,
                              void* d_out, int out_size) {
    const float* xyz    = (const float*)d_in[0];
    const float* planes = (const float*)d_in[1];
    const float* lines  = (const float*)d_in[2];
    const float* w1     = (const float*)d_in[3];
    const float* b1     = (const float*)d_in[4];
    const float* w2     = (const float*)d_in[5];
    const float* b2     = (const float*)d_in[6];
    float* out = (float*)d_out;

    cudaFuncSetAttribute(tensosdf_main_kernel,
                         cudaFuncAttributeMaxDynamicSharedMemorySize, SMEM_BYTES);

    transpose_planes_kernel<<<3 * GRID_D * 10, 256>>>(planes);

    const int prep_total = IN_PAD * SDF_DIM + SDF_DIM * OUT_PAD + 3 * GRID_D * NCOMP;
    prep_small_kernel<<<(prep_total + 255) / 256, 256>>>(w1, w2, lines);

    tensosdf_main_kernel<<<NBLK, NTHR, SMEM_BYTES>>>(xyz, b1, b2, out);
}

// round 8
// speedup vs baseline: 4.4718x; 2.9819x over previous
#include <cuda_runtime.h>
#include <cuda_fp16.h>
#include <math.h>
#include <stdint.h>

// ---------------- problem constants ----------------
#define NPTS    524288
#define GRID_D  300
#define NCOMP   36
#define SDF_DIM 256
#define OUT_CH  129
#define K1      144       // GEMM1 K (129 used + pad), 9 k-steps
#define AP      152       // A / W1 smem pitch in halves (304B = 48 mod 128 -> conflict-free)
#define N2P     160       // GEMM2 N padded (129 used), 20 n-tiles
#define K2      256       // GEMM2 K, 16 k-steps
#define HP      264       // H / W2 smem pitch in halves (528B = 16 mod 128)
#define TILE_M  64
#define NTILES  (NPTS / TILE_M)   // 8192
#define NTHR    256

// ---------------- smem layout (bytes) ----------------
#define SM_A   0
#define SM_H   (SM_A + TILE_M * AP * 2)       // 19456
#define SM_W1  (SM_H + TILE_M * HP * 2)       // 53248
#define SM_W2  (SM_W1 + SDF_DIM * AP * 2)     // 131072
#define SM_B2  (SM_W2 + N2P * HP * 2)         // 215552
#define SM_TOTAL (SM_B2 + N2P * 4)            // 216192

// ---------------- scratch globals ----------------
__device__ __align__(16) float  g_planesT[3 * GRID_D * GRID_D * NCOMP]; // [p][y][x][c]
__device__ __align__(16) float  g_linesT[3 * GRID_D * NCOMP];           // [p][z][c]
__device__ __align__(16) __half g_w1h[SDF_DIM * K1];                    // [j][k]  (permuted, bias row k=129)
__device__ __align__(16) __half g_w2h[N2P * K2];                        // [o][j]  (rows >=129 zero)

// ---------------- PTX helpers (sm_80-era, compile on plain sm_103) ----------------
__device__ __forceinline__ uint32_t smem_to_u32(const void* p) {
    uint32_t a;
    asm("{ .reg .u64 t; cvta.to.shared.u64 t, %1; cvt.u32.u64 %0, t; }" : "=r"(a) : "l"(p));
    return a;
}
__device__ __forceinline__ void ldm_x4(uint32_t& r0, uint32_t& r1, uint32_t& r2, uint32_t& r3, uint32_t addr) {
    asm volatile("ldmatrix.sync.aligned.m8n8.x4.shared.b16 {%0,%1,%2,%3}, [%4];"
                 : "=r"(r0), "=r"(r1), "=r"(r2), "=r"(r3) : "r"(addr));
}
__device__ __forceinline__ void ldm_x2(uint32_t& r0, uint32_t& r1, uint32_t addr) {
    asm volatile("ldmatrix.sync.aligned.m8n8.x2.shared.b16 {%0,%1}, [%2];"
                 : "=r"(r0), "=r"(r1) : "r"(addr));
}
__device__ __forceinline__ void mma16816(float* c, const uint32_t* a, uint32_t b0, uint32_t b1) {
    asm volatile("mma.sync.aligned.m16n8k16.row.col.f32.f16.f16.f32 "
                 "{%0,%1,%2,%3}, {%4,%5,%6,%7}, {%8,%9}, {%0,%1,%2,%3};"
                 : "+f"(c[0]), "+f"(c[1]), "+f"(c[2]), "+f"(c[3])
                 : "r"(a[0]), "r"(a[1]), "r"(a[2]), "r"(a[3]), "r"(b0), "r"(b1));
}

// ---------------- preprocess: plane transpose [3][36][300][300] -> [3][300][300][36] ----------------
__global__ void transpose_planes_kernel(const float* __restrict__ planes) {
    int b = blockIdx.x;
    int xt = b % 10;
    int rest = b / 10;
    int y = rest % GRID_D;
    int p = rest / GRID_D;
    int x0 = xt * 32;
    __shared__ float tile[NCOMP][33];
    for (int idx = threadIdx.x; idx < NCOMP * 32; idx += blockDim.x) {
        int c = idx >> 5, xx = idx & 31;
        if (x0 + xx < GRID_D)
            tile[c][xx] = planes[((p * NCOMP + c) * GRID_D + y) * GRID_D + x0 + xx];
    }
    __syncthreads();
    for (int idx = threadIdx.x; idx < 32 * NCOMP; idx += blockDim.x) {
        int xx = idx / NCOMP, c = idx % NCOMP;
        if (x0 + xx < GRID_D)
            g_planesT[((p * GRID_D + y) * GRID_D + (x0 + xx)) * NCOMP + c] = tile[c][xx];
    }
}

// ---------------- preprocess: fp16 weights (permuted, bias-folded) + lines transpose ----------------
// A channel order: k 0..107 = feat (orig mlp_in 21..128), k 108..128 = embed (orig 0..20),
//                  k 129 = bias row (A=1, W1=b1), k 130..143 = 0.
__global__ void prep_small_kernel(const float* __restrict__ w1, const float* __restrict__ b1,
                                  const float* __restrict__ w2,
                                  const float* __restrict__ lines) {
    int i = blockIdx.x * blockDim.x + threadIdx.x;
    const int W1N = SDF_DIM * K1;       // 36864
    const int W2N = N2P * K2;           // 40960
    const int LNT = 3 * GRID_D * NCOMP; // 32400
    if (i < W1N) {
        int j = i / K1, k = i % K1;
        float v = 0.0f;
        if (k < 108)       v = w1[j * OUT_CH + 21 + k];
        else if (k < 129)  v = w1[j * OUT_CH + (k - 108)];
        else if (k == 129) v = b1[j];
        g_w1h[i] = __float2half_rn(v);
    } else if (i < W1N + W2N) {
        int t = i - W1N;
        int o = t / K2, j = t % K2;
        g_w2h[t] = __float2half_rn((o < OUT_CH) ? w2[o * SDF_DIM + j] : 0.0f);
    } else if (i < W1N + W2N + LNT) {
        int t = i - W1N - W2N;
        int c = t % NCOMP;
        int z = (t / NCOMP) % GRID_D;
        int p = t / (NCOMP * GRID_D);
        g_linesT[t] = lines[(p * NCOMP + c) * GRID_D + z];
    }
}

// ---------------- activation: softplus(100u)/100 (MUFU ex2/lg2 path) ----------------
__device__ __forceinline__ float actf(float u) {
    float t = 100.0f * u;
    return (fmaxf(t, 0.0f) + __logf(1.0f + __expf(-fabsf(t)))) * 0.01f;
}

// ---------------- persistent fused main kernel ----------------
__global__ __launch_bounds__(NTHR)
void tensosdf_main_kernel(const float* __restrict__ xyz,
                          const float* __restrict__ b2,
                          float* __restrict__ out) {
    extern __shared__ char smem[];
    const uint32_t su = smem_to_u32(smem);
    const int tid  = threadIdx.x;
    const int wid  = tid >> 5;
    const int lane = tid & 31;
    float* b2s = (float*)(smem + SM_B2);

    // ---- stage weights into smem once per CTA ----
    {
        __half* sW1 = (__half*)(smem + SM_W1);
        __half* sW2 = (__half*)(smem + SM_W2);
        for (int i = tid; i < SDF_DIM * K1; i += NTHR) {
            int j = i / K1, k = i % K1;
            sW1[j * AP + k] = g_w1h[i];
        }
        for (int i = tid; i < N2P * K2; i += NTHR) {
            int o = i >> 8, j = i & 255;
            sW2[o * HP + j] = g_w2h[i];
        }
        if (tid < N2P) b2s[tid] = (tid < OUT_CH) ? b2[tid] : 0.0f;
    }
    __syncthreads();

    const int mw = wid >> 2;   // 0..1 : 32-point m-slab
    const int nw = wid & 3;    // 0..3 : n-slab
    const int g  = lane >> 2;  // mma C-frag row group
    const int tq = lane & 3;   // mma C-frag col pair

    // ldmatrix lane address components
    const int a_row  = (lane & 15);
    const int a_koff = (lane >> 4) * 8;          // halves
    const int b_row  = (lane & 7);
    const int b_koff = ((lane >> 3) & 1) * 8;    // halves

    for (int tile = blockIdx.x; tile < NTILES; tile += gridDim.x) {
        const int pt0 = tile * TILE_M;

        // ======== Phase A: gather + embed -> A smem (fp16) ========
        if (tid < 192) {
            int point = tid / 3;
            int p     = tid - point * 3;
            int gp = pt0 + point;
            float x = xyz[gp * 3 + 0];
            float y = xyz[gp * 3 + 1];
            float z = xyz[gp * 3 + 2];
            float sx, sy, sz;
            if (p == 0)      { sx = x; sy = y; sz = z; }
            else if (p == 1) { sx = x; sy = z; sz = y; }
            else             { sx = y; sy = z; sz = x; }
            const float HALF = 0.5f * (GRID_D - 1);
            float fx = (sx + 1.0f) * HALF;
            float fy = (sy + 1.0f) * HALF;
            float fz = (sz + 1.0f) * HALF;
            int x0 = min(max((int)floorf(fx), 0), GRID_D - 2);
            int y0 = min(max((int)floorf(fy), 0), GRID_D - 2);
            int z0 = min(max((int)floorf(fz), 0), GRID_D - 2);
            float tx = fx - (float)x0;
            float ty = fy - (float)y0;
            float tz = fz - (float)z0;
            float w00 = (1.0f - tx) * (1.0f - ty);
            float w01 = tx * (1.0f - ty);
            float w10 = (1.0f - tx) * ty;
            float w11 = tx * ty;
            const float4* base = (const float4*)(g_planesT + (size_t)((p * GRID_D + y0) * GRID_D + x0) * NCOMP);
            const float4* lb   = (const float4*)(g_linesT + (size_t)(p * GRID_D + z0) * NCOMP);
            char* dst = smem + SM_A + point * (AP * 2) + p * 72;   // feat k-block [p*36, p*36+36)
            #pragma unroll
            for (int cc = 0; cc < 9; cc++) {
                float4 v00 = base[cc];
                float4 v01 = base[9 + cc];
                float4 v10 = base[2700 + cc];
                float4 v11 = base[2709 + cc];
                float4 l0 = lb[cc];
                float4 l1 = lb[9 + cc];
                float rx = (v00.x * w00 + v01.x * w01 + v10.x * w10 + v11.x * w11) * (l0.x + (l1.x - l0.x) * tz);
                float ry = (v00.y * w00 + v01.y * w01 + v10.y * w10 + v11.y * w11) * (l0.y + (l1.y - l0.y) * tz);
                float rz = (v00.z * w00 + v01.z * w01 + v10.z * w10 + v11.z * w11) * (l0.z + (l1.z - l0.z) * tz);
                float rw = (v00.w * w00 + v01.w * w01 + v10.w * w10 + v11.w * w11) * (l0.w + (l1.w - l0.w) * tz);
                __half2 h0 = __floats2half2_rn(rx, ry);
                __half2 h1 = __floats2half2_rn(rz, rw);
                uint2 pk;
                pk.x = *(uint32_t*)&h0;
                pk.y = *(uint32_t*)&h1;
                *(uint2*)(dst + cc * 8) = pk;
            }
        } else {
            int point = tid - 192;
            int gp = pt0 + point;
            float vx = xyz[gp * 3 + 0];
            float vy = xyz[gp * 3 + 1];
            float vz = xyz[gp * 3 + 2];
            float e[22];
            e[0] = vx; e[1] = vy; e[2] = vz;
            #pragma unroll
            for (int d = 0; d < 3; d++) {
                float v = (d == 0) ? vx : (d == 1) ? vy : vz;
                #pragma unroll
                for (int f = 0; f < 3; f++) {
                    float s, c;
                    sincosf(v * (float)(1 << f), &s, &c);
                    e[3 + d * 3 + f]  = s;
                    e[12 + d * 3 + f] = c;
                }
            }
            e[21] = 1.0f;  // bias row at k=129
            char* dst = smem + SM_A + point * (AP * 2) + 108 * 2;  // k 108..143 = 18 half2
            #pragma unroll
            for (int i = 0; i < 18; i++) {
                int k0 = 108 + 2 * i;
                float lo = (k0 <= 129) ? e[k0 - 108] : 0.0f;
                float hi = (k0 + 1 <= 129) ? e[k0 + 1 - 108] : 0.0f;
                __half2 h = __floats2half2_rn(lo, hi);
                *(uint32_t*)(dst + i * 4) = *(uint32_t*)&h;
            }
        }
        __syncthreads();

        // ======== GEMM1: H = act(A @ W1^T), warp = [mw*32..+32) x [nw*64..+64) ========
        {
            // preload A fragments: 2 m-tiles x 9 k-steps
            uint32_t Af[2][9][4];
            const uint32_t a_base = su + SM_A + (uint32_t)(mw * 32 + a_row) * (AP * 2) + (uint32_t)a_koff * 2;
            #pragma unroll
            for (int t = 0; t < 2; t++)
                #pragma unroll
                for (int s = 0; s < 9; s++)
                    ldm_x4(Af[t][s][0], Af[t][s][1], Af[t][s][2], Af[t][s][3],
                           a_base + (uint32_t)t * 16 * (AP * 2) + (uint32_t)s * 32);

            const uint32_t b_base = su + SM_W1 + (uint32_t)(nw * 64 + b_row) * (AP * 2) + (uint32_t)b_koff * 2;
            #pragma unroll
            for (int jt = 0; jt < 8; jt++) {
                float acc[2][4] = {{0,0,0,0},{0,0,0,0}};
                #pragma unroll
                for (int s = 0; s < 9; s++) {
                    uint32_t b0, b1v;
                    ldm_x2(b0, b1v, b_base + (uint32_t)jt * 8 * (AP * 2) + (uint32_t)s * 32);
                    mma16816(acc[0], Af[0][s], b0, b1v);
                    mma16816(acc[1], Af[1][s], b0, b1v);
                }
                // epilogue: softplus -> H fp16
                #pragma unroll
                for (int t = 0; t < 2; t++) {
                    __half2 hlo = __floats2half2_rn(actf(acc[t][0]), actf(acc[t][1]));
                    __half2 hhi = __floats2half2_rn(actf(acc[t][2]), actf(acc[t][3]));
                    char* hp0 = smem + SM_H + (mw * 32 + t * 16 + g) * (HP * 2)
                              + (nw * 64 + jt * 8 + tq * 2) * 2;
                    *(uint32_t*)hp0 = *(uint32_t*)&hlo;
                    *(uint32_t*)(hp0 + 8 * (HP * 2)) = *(uint32_t*)&hhi;
                }
            }
        }
        __syncthreads();

        // ======== GEMM2: out = H @ W2^T + b2, warp = [mw*32..+32) x [nw*40..+40) ========
        {
            const uint32_t h_base = su + SM_H + (uint32_t)(mw * 32 + a_row) * (HP * 2) + (uint32_t)a_koff * 2;
            const uint32_t w2_base = su + SM_W2 + (uint32_t)b_row * (HP * 2) + (uint32_t)b_koff * 2;
            #pragma unroll 1
            for (int t = 0; t < 2; t++) {
                uint32_t Hf[16][4];
                #pragma unroll
                for (int s = 0; s < 16; s++)
                    ldm_x4(Hf[s][0], Hf[s][1], Hf[s][2], Hf[s][3],
                           h_base + (uint32_t)t * 16 * (HP * 2) + (uint32_t)s * 32);
                #pragma unroll 1
                for (int j = 0; j < 5; j++) {
                    const int o_base = nw * 40 + j * 8;
                    float acc[4] = {0, 0, 0, 0};
                    const uint32_t wb = w2_base + (uint32_t)o_base * (HP * 2);
                    #pragma unroll
                    for (int s = 0; s < 16; s++) {
                        uint32_t b0, b1v;
                        ldm_x2(b0, b1v, wb + (uint32_t)s * 32);
                        mma16816(acc, Hf[s], b0, b1v);
                    }
                    // epilogue: + b2 -> global
                    const int oc = o_base + tq * 2;
                    const int pr = pt0 + mw * 32 + t * 16 + g;
                    if (oc < OUT_CH) {
                        out[(size_t)pr * OUT_CH + oc] = acc[0] + b2s[oc];
                        out[(size_t)(pr + 8) * OUT_CH + oc] = acc[2] + b2s[oc];
                    }
                    if (oc + 1 < OUT_CH) {
                        out[(size_t)pr * OUT_CH + oc + 1] = acc[1] + b2s[oc + 1];
                        out[(size_t)(pr + 8) * OUT_CH + oc + 1] = acc[3] + b2s[oc + 1];
                    }
                }
            }
        }
        __syncthreads();
    }
}

// ---------------- launch ----------------
extern "C" void kernel_launch(void* const* d_in, const int* in_sizes, int n_in,
                              void* d_out, int out_size) {
    const float* xyz    = (const float*)d_in[0];
    const float* planes = (const float*)d_in[1];
    const float* lines  = (const float*)d_in[2];
    const float* w1     = (const float*)d_in[3];
    const float* b1     = (const float*)d_in[4];
    const float* w2     = (const float*)d_in[5];
    const float* b2     = (const float*)d_in[6];
    float* out = (float*)d_out;

    int nsm = 148;
    cudaDeviceGetAttribute(&nsm, cudaDevAttrMultiProcessorCount, 0);

    cudaFuncSetAttribute(tensosdf_main_kernel,
                         cudaFuncAttributeMaxDynamicSharedMemorySize, SM_TOTAL);

    transpose_planes_kernel<<<3 * GRID_D * 10, 256>>>(planes);

    const int prep_total = SDF_DIM * K1 + N2P * K2 + 3 * GRID_D * NCOMP;
    prep_small_kernel<<<(prep_total + 255) / 256, 256>>>(w1, b1, w2, lines);

    tensosdf_main_kernel<<<nsm, NTHR, SM_TOTAL>>>(xyz, b2, out);
}

// round 9
// speedup vs baseline: 7.1570x; 1.6005x over previous
#include <cuda_runtime.h>
#include <cuda_fp16.h>
#include <math.h>
#include <stdint.h>

// ---------------- problem constants ----------------
#define NPTS    524288
#define GRID_D  300
#define NCOMP   36
#define CPAD    40        // channel dim padded to 40 halves (80B, 16B-aligned corners)
#define SDF_DIM 256
#define OUT_CH  129
#define K1      144       // GEMM1 K (129 used + pad), 9 k-steps
#define AP      152       // A / W1 smem pitch in halves (304B -> conflict-free ldmatrix)
#define N2P     136       // GEMM2 N padded (129 used), 17 n-tiles of 8
#define K2      256       // GEMM2 K, 16 k-steps
#define HP      264       // H / W2 smem pitch in halves (528B -> conflict-free)
#define TILE_M  96
#define NTILES  ((NPTS + TILE_M - 1) / TILE_M)   // 5462 (last tile partial: 32 pts)
#define NTHR    384

// ---------------- smem layout (bytes) ----------------
#define SM_A   0
#define SM_H   (SM_A + TILE_M * AP * 2)       // 29184
#define SM_W1  (SM_H + TILE_M * HP * 2)       // +50688 = 79872
#define SM_W2  (SM_W1 + SDF_DIM * AP * 2)     // +77824 = 157696
#define SM_B2  (SM_W2 + N2P * HP * 2)         // +71808 = 229504
#define SM_TOTAL (SM_B2 + N2P * 4)            // 230048

// ---------------- scratch globals ----------------
__device__ __align__(16) __half g_planesTh[3 * GRID_D * GRID_D * CPAD]; // [p][y][x][c40] fp16
__device__ __align__(16) __half g_linesTh[3 * GRID_D * CPAD];           // [p][z][c40] fp16
__device__ __align__(16) __half g_w1h[SDF_DIM * K1];                    // [j][k] (permuted, bias row k=129)
__device__ __align__(16) __half g_w2h[N2P * K2];                        // [o][j] (rows >=129 zero)

// ---------------- PTX helpers (sm_80-era, compile on plain sm_103) ----------------
__device__ __forceinline__ uint32_t smem_to_u32(const void* p) {
    uint32_t a;
    asm("{ .reg .u64 t; cvta.to.shared.u64 t, %1; cvt.u32.u64 %0, t; }" : "=r"(a) : "l"(p));
    return a;
}
__device__ __forceinline__ void ldm_x4(uint32_t& r0, uint32_t& r1, uint32_t& r2, uint32_t& r3, uint32_t addr) {
    asm volatile("ldmatrix.sync.aligned.m8n8.x4.shared.b16 {%0,%1,%2,%3}, [%4];"
                 : "=r"(r0), "=r"(r1), "=r"(r2), "=r"(r3) : "r"(addr));
}
__device__ __forceinline__ void ldm_x2(uint32_t& r0, uint32_t& r1, uint32_t addr) {
    asm volatile("ldmatrix.sync.aligned.m8n8.x2.shared.b16 {%0,%1}, [%2];"
                 : "=r"(r0), "=r"(r1) : "r"(addr));
}
__device__ __forceinline__ void mma16816(float* c, const uint32_t* a, uint32_t b0, uint32_t b1) {
    asm volatile("mma.sync.aligned.m16n8k16.row.col.f32.f16.f16.f32 "
                 "{%0,%1,%2,%3}, {%4,%5,%6,%7}, {%8,%9}, {%0,%1,%2,%3};"
                 : "+f"(c[0]), "+f"(c[1]), "+f"(c[2]), "+f"(c[3])
                 : "r"(a[0]), "r"(a[1]), "r"(a[2]), "r"(a[3]), "r"(b0), "r"(b1));
}

// ---------------- preprocess: planes -> fp16 [3][300][300][40] ----------------
__global__ void transpose_planes_kernel(const float* __restrict__ planes) {
    int b = blockIdx.x;
    int xt = b % 10;
    int rest = b / 10;
    int y = rest % GRID_D;
    int p = rest / GRID_D;
    int x0 = xt * 32;
    __shared__ float tile[NCOMP][33];
    for (int idx = threadIdx.x; idx < NCOMP * 32; idx += blockDim.x) {
        int c = idx >> 5, xx = idx & 31;
        if (x0 + xx < GRID_D)
            tile[c][xx] = planes[((p * NCOMP + c) * GRID_D + y) * GRID_D + x0 + xx];
    }
    __syncthreads();
    for (int idx = threadIdx.x; idx < 32 * NCOMP; idx += blockDim.x) {
        int xx = idx / NCOMP, c = idx % NCOMP;
        if (x0 + xx < GRID_D)
            g_planesTh[((size_t)(p * GRID_D + y) * GRID_D + (x0 + xx)) * CPAD + c] =
                __float2half_rn(tile[c][xx]);
    }
}

// ---------------- preprocess: fp16 weights (permuted, bias-folded) + fp16 lines ----------------
// A channel order: k 0..107 = feat (orig mlp_in 21..128), k 108..128 = embed (orig 0..20),
//                  k 129 = bias row (A=1, W1=b1), k 130..143 = 0.
__global__ void prep_small_kernel(const float* __restrict__ w1, const float* __restrict__ b1,
                                  const float* __restrict__ w2,
                                  const float* __restrict__ lines) {
    int i = blockIdx.x * blockDim.x + threadIdx.x;
    const int W1N = SDF_DIM * K1;        // 36864
    const int W2N = N2P * K2;            // 34816
    const int LNT = 3 * GRID_D * CPAD;   // 36000
    if (i < W1N) {
        int j = i / K1, k = i % K1;
        float v = 0.0f;
        if (k < 108)       v = w1[j * OUT_CH + 21 + k];
        else if (k < 129)  v = w1[j * OUT_CH + (k - 108)];
        else if (k == 129) v = b1[j];
        g_w1h[i] = __float2half_rn(v);
    } else if (i < W1N + W2N) {
        int t = i - W1N;
        int o = t / K2, j = t % K2;
        g_w2h[t] = __float2half_rn((o < OUT_CH) ? w2[o * SDF_DIM + j] : 0.0f);
    } else if (i < W1N + W2N + LNT) {
        int t = i - W1N - W2N;
        int c = t % CPAD;
        int z = (t / CPAD) % GRID_D;
        int p = t / (CPAD * GRID_D);
        g_linesTh[t] = __float2half_rn((c < NCOMP) ? lines[(p * NCOMP + c) * GRID_D + z] : 0.0f);
    }
}

// ---------------- activation: softplus(100u)/100 ----------------
__device__ __forceinline__ float actf(float u) {
    float t = 100.0f * u;
    return (fmaxf(t, 0.0f) + __logf(1.0f + __expf(-fabsf(t)))) * 0.01f;
}

union V10 { uint4 u[10]; __half2 h[40]; };

// ---------------- persistent fused main kernel ----------------
__global__ __launch_bounds__(NTHR)
void tensosdf_main_kernel(const float* __restrict__ xyz,
                          const float* __restrict__ b2,
                          float* __restrict__ out) {
    extern __shared__ char smem[];
    const uint32_t su = smem_to_u32(smem);
    const int tid  = threadIdx.x;
    const int wid  = tid >> 5;
    const int lane = tid & 31;
    float* b2s = (float*)(smem + SM_B2);

    // ---- stage weights into smem once per CTA ----
    {
        __half* sW1 = (__half*)(smem + SM_W1);
        __half* sW2 = (__half*)(smem + SM_W2);
        for (int i = tid; i < SDF_DIM * K1; i += NTHR) {
            int j = i / K1, k = i % K1;
            sW1[j * AP + k] = g_w1h[i];
        }
        for (int i = tid; i < N2P * K2; i += NTHR) {
            int o = i >> 8, j = i & 255;
            sW2[o * HP + j] = g_w2h[i];
        }
        if (tid < N2P) b2s[tid] = (tid < OUT_CH) ? b2[tid] : 0.0f;
    }
    __syncthreads();

    const int mw = wid >> 2;   // 0..2 : 32-point m-slab
    const int nw = wid & 3;    // 0..3 : n-slab
    const int g  = lane >> 2;  // mma C-frag row group
    const int tq = lane & 3;   // mma C-frag col pair

    const int a_row  = (lane & 15);
    const int a_koff = (lane >> 4) * 8;          // halves
    const int b_row  = (lane & 7);
    const int b_koff = ((lane >> 3) & 1) * 8;    // halves

    for (int tile = blockIdx.x; tile < NTILES; tile += gridDim.x) {
        const int pt0 = tile * TILE_M;

        // ======== Phase A: gather + embed -> A smem (fp16) ========
        if (tid < 288) {
            int point = tid / 3;
            int p     = tid - point * 3;
            int gp = pt0 + point;
            if (gp >= NPTS) gp = NPTS - 1;
            float x = xyz[gp * 3 + 0];
            float y = xyz[gp * 3 + 1];
            float z = xyz[gp * 3 + 2];
            float sx, sy, sz;
            if (p == 0)      { sx = x; sy = y; sz = z; }
            else if (p == 1) { sx = x; sy = z; sz = y; }
            else             { sx = y; sy = z; sz = x; }
            const float HALF = 0.5f * (GRID_D - 1);
            float fx = (sx + 1.0f) * HALF;
            float fy = (sy + 1.0f) * HALF;
            float fz = (sz + 1.0f) * HALF;
            int x0 = min(max((int)floorf(fx), 0), GRID_D - 2);
            int y0 = min(max((int)floorf(fy), 0), GRID_D - 2);
            int z0 = min(max((int)floorf(fz), 0), GRID_D - 2);
            float tx = fx - (float)x0;
            float ty = fy - (float)y0;
            float tz = fz - (float)z0;
            float w00 = (1.0f - tx) * (1.0f - ty);
            float w01 = tx * (1.0f - ty);
            float w10 = (1.0f - tx) * ty;
            float w11 = tx * ty;

            // row-pair loads: x0,x0+1 contiguous (2*40 halves = 10 uint4), rows y0 / y0+1
            const uint4* r0p = (const uint4*)(g_planesTh + ((size_t)(p * GRID_D + y0) * GRID_D + x0) * CPAD);
            const uint4* lp  = (const uint4*)(g_linesTh + (size_t)(p * GRID_D + z0) * CPAD);
            V10 R0, R1, RL;
            #pragma unroll
            for (int i = 0; i < 10; i++) R0.u[i] = r0p[i];
            #pragma unroll
            for (int i = 0; i < 10; i++) R1.u[i] = r0p[GRID_D * CPAD / 8 + i];  // +1 y-row = 1500 uint4
            #pragma unroll
            for (int i = 0; i < 10; i++) RL.u[i] = lp[i];   // z0 (5) + z0+1 (5)

            char* dst = smem + SM_A + point * (AP * 2) + p * NCOMP * 2;
            #pragma unroll
            for (int cc = 0; cc < 9; cc++) {
                uint2 pk;
                #pragma unroll
                for (int half_q = 0; half_q < 2; half_q++) {
                    int hi2 = 2 * cc + half_q;   // half2 index within a 40-half corner
                    float2 v00 = __half22float2(R0.h[hi2]);
                    float2 v01 = __half22float2(R0.h[20 + hi2]);
                    float2 v10 = __half22float2(R1.h[hi2]);
                    float2 v11 = __half22float2(R1.h[20 + hi2]);
                    float2 l0  = __half22float2(RL.h[hi2]);
                    float2 l1  = __half22float2(RL.h[20 + hi2]);
                    float ra = (v00.x * w00 + v01.x * w01 + v10.x * w10 + v11.x * w11)
                             * (l0.x + (l1.x - l0.x) * tz);
                    float rb = (v00.y * w00 + v01.y * w01 + v10.y * w10 + v11.y * w11)
                             * (l0.y + (l1.y - l0.y) * tz);
                    __half2 hh = __floats2half2_rn(ra, rb);
                    if (half_q == 0) pk.x = *(uint32_t*)&hh; else pk.y = *(uint32_t*)&hh;
                }
                *(uint2*)(dst + cc * 8) = pk;
            }
        } else {
            int point = tid - 288;
            int gp = pt0 + point;
            if (gp >= NPTS) gp = NPTS - 1;
            float vx = xyz[gp * 3 + 0];
            float vy = xyz[gp * 3 + 1];
            float vz = xyz[gp * 3 + 2];
            float e[22];
            e[0] = vx; e[1] = vy; e[2] = vz;
            #pragma unroll
            for (int d = 0; d < 3; d++) {
                float v = (d == 0) ? vx : (d == 1) ? vy : vz;
                #pragma unroll
                for (int f = 0; f < 3; f++) {
                    float s, c;
                    sincosf(v * (float)(1 << f), &s, &c);
                    e[3 + d * 3 + f]  = s;
                    e[12 + d * 3 + f] = c;
                }
            }
            e[21] = 1.0f;  // bias row at k=129
            char* dst = smem + SM_A + point * (AP * 2) + 108 * 2;  // k 108..143 = 18 half2
            #pragma unroll
            for (int i = 0; i < 18; i++) {
                int k0 = 108 + 2 * i;
                float lo = (k0 <= 129) ? e[k0 - 108] : 0.0f;
                float hi = (k0 + 1 <= 129) ? e[k0 + 1 - 108] : 0.0f;
                __half2 h = __floats2half2_rn(lo, hi);
                *(uint32_t*)(dst + i * 4) = *(uint32_t*)&h;
            }
        }
        __syncthreads();

        // ======== GEMM1: H = act(A @ W1^T), warp = [mw*32..+32) x [nw*64..+64) ========
        {
            uint32_t Af[2][9][4];
            const uint32_t a_base = su + SM_A + (uint32_t)(mw * 32 + a_row) * (AP * 2) + (uint32_t)a_koff * 2;
            #pragma unroll
            for (int t = 0; t < 2; t++)
                #pragma unroll
                for (int s = 0; s < 9; s++)
                    ldm_x4(Af[t][s][0], Af[t][s][1], Af[t][s][2], Af[t][s][3],
                           a_base + (uint32_t)t * 16 * (AP * 2) + (uint32_t)s * 32);

            const uint32_t b_base = su + SM_W1 + (uint32_t)(nw * 64 + b_row) * (AP * 2) + (uint32_t)b_koff * 2;
            #pragma unroll
            for (int jt = 0; jt < 8; jt++) {
                float acc[2][4] = {{0,0,0,0},{0,0,0,0}};
                #pragma unroll
                for (int s = 0; s < 9; s++) {
                    uint32_t b0, b1v;
                    ldm_x2(b0, b1v, b_base + (uint32_t)jt * 8 * (AP * 2) + (uint32_t)s * 32);
                    mma16816(acc[0], Af[0][s], b0, b1v);
                    mma16816(acc[1], Af[1][s], b0, b1v);
                }
                #pragma unroll
                for (int t = 0; t < 2; t++) {
                    __half2 hlo = __floats2half2_rn(actf(acc[t][0]), actf(acc[t][1]));
                    __half2 hhi = __floats2half2_rn(actf(acc[t][2]), actf(acc[t][3]));
                    char* hp0 = smem + SM_H + (mw * 32 + t * 16 + g) * (HP * 2)
                              + (nw * 64 + jt * 8 + tq * 2) * 2;
                    *(uint32_t*)hp0 = *(uint32_t*)&hlo;
                    *(uint32_t*)(hp0 + 8 * (HP * 2)) = *(uint32_t*)&hhi;
                }
            }
        }
        __syncthreads();

        // ======== GEMM2: out = H @ W2^T + b2, 17 n-tiles split 5/4/4/4 over nw ========
        {
            const uint32_t h_base = su + SM_H + (uint32_t)(mw * 32 + a_row) * (HP * 2) + (uint32_t)a_koff * 2;
            const uint32_t w2_base = su + SM_W2 + (uint32_t)b_row * (HP * 2) + (uint32_t)b_koff * 2;
            #pragma unroll 1
            for (int t = 0; t < 2; t++) {
                uint32_t Hf[16][4];
                #pragma unroll
                for (int s = 0; s < 16; s++)
                    ldm_x4(Hf[s][0], Hf[s][1], Hf[s][2], Hf[s][3],
                           h_base + (uint32_t)t * 16 * (HP * 2) + (uint32_t)s * 32);
                #pragma unroll 1
                for (int j5 = 0; j5 < 5; j5++) {
                    const int jt = nw + j5 * 4;
                    if (jt >= 17) break;
                    const int o_base = jt * 8;
                    float acc[4] = {0, 0, 0, 0};
                    const uint32_t wb = w2_base + (uint32_t)o_base * (HP * 2);
                    #pragma unroll
                    for (int s = 0; s < 16; s++) {
                        uint32_t b0, b1v;
                        ldm_x2(b0, b1v, wb + (uint32_t)s * 32);
                        mma16816(acc, Hf[s], b0, b1v);
                    }
                    const int oc = o_base + tq * 2;
                    const int pr = pt0 + mw * 32 + t * 16 + g;
                    if (pr < NPTS && oc < OUT_CH) {
                        out[(size_t)pr * OUT_CH + oc] = acc[0] + b2s[oc];
                        if (oc + 1 < OUT_CH)
                            out[(size_t)pr * OUT_CH + oc + 1] = acc[1] + b2s[oc + 1];
                    }
                    if (pr + 8 < NPTS && oc < OUT_CH) {
                        out[(size_t)(pr + 8) * OUT_CH + oc] = acc[2] + b2s[oc];
                        if (oc + 1 < OUT_CH)
                            out[(size_t)(pr + 8) * OUT_CH + oc + 1] = acc[3] + b2s[oc + 1];
                    }
                }
            }
        }
        __syncthreads();
    }
}

// ---------------- launch ----------------
extern "C" void kernel_launch(void* const* d_in, const int* in_sizes, int n_in,
                              void* d_out, int out_size) {
    const float* xyz    = (const float*)d_in[0];
    const float* planes = (const float*)d_in[1];
    const float* lines  = (const float*)d_in[2];
    const float* w1     = (const float*)d_in[3];
    const float* b1     = (const float*)d_in[4];
    const float* w2     = (const float*)d_in[5];
    const float* b2     = (const float*)d_in[6];
    float* out = (float*)d_out;

    int nsm = 148;
    cudaDeviceGetAttribute(&nsm, cudaDevAttrMultiProcessorCount, 0);

    cudaFuncSetAttribute(tensosdf_main_kernel,
                         cudaFuncAttributeMaxDynamicSharedMemorySize, SM_TOTAL);

    transpose_planes_kernel<<<3 * GRID_D * 10, 256>>>(planes);

    const int prep_total = SDF_DIM * K1 + N2P * K2 + 3 * GRID_D * CPAD;
    prep_small_kernel<<<(prep_total + 255) / 256, 256>>>(w1, b1, w2, lines);

    tensosdf_main_kernel<<<nsm, NTHR, SM_TOTAL>>>(xyz, b2, out);
}

// round 11
// speedup vs baseline: 7.4745x; 1.0444x over previous
#include <cuda_runtime.h>
#include <cuda_fp16.h>
#include <math.h>
#include <stdint.h>

// ---------------- problem constants ----------------
#define NPTS    524288
#define GRID_D  300
#define NCOMP   36
#define CPAD    40        // channel dim padded to 40 halves (80B, 16B-aligned corners)
#define SDF_DIM 256
#define OUT_CH  129
#define K1      144       // GEMM1 K (129 used + pad), 9 k-steps
#define AP      152       // A / W1 smem pitch in halves (304B -> conflict-free ldmatrix)
#define N2P     136       // GEMM2 N padded (129 used), 17 n-tiles of 8
#define K2      256       // GEMM2 K, 16 k-steps
#define HP      264       // H / W2 smem pitch in halves (528B -> conflict-free)
#define TILE_M  96
#define NTILES  ((NPTS + TILE_M - 1) / TILE_M)   // 5462 (last tile partial: 32 pts)
#define NTHR    384

// ---------------- smem layout (bytes) ----------------
#define SM_A   0
#define SM_H   (SM_A + TILE_M * AP * 2)       // 29184
#define SM_W1  (SM_H + TILE_M * HP * 2)       // +50688 = 79872
#define SM_W2  (SM_W1 + SDF_DIM * AP * 2)     // +77824 = 157696
#define SM_B2  (SM_W2 + N2P * HP * 2)         // +71808 = 229504
#define SM_TOTAL (SM_B2 + N2P * 4)            // 230048

// ---------------- scratch globals ----------------
__device__ __align__(16) __half g_planesTh[3 * GRID_D * GRID_D * CPAD]; // [p][y][x][c40] fp16
__device__ __align__(16) __half g_linesTh[3 * GRID_D * CPAD];           // [p][z][c40] fp16
__device__ __align__(16) __half g_w1h[SDF_DIM * K1];                    // [j][k] (permuted, bias row k=129)
__device__ __align__(16) __half g_w2h[N2P * K2];                        // [o][j] (rows >=129 zero)

// ---------------- PTX helpers (sm_80-era, compile on plain sm_103) ----------------
__device__ __forceinline__ uint32_t smem_to_u32(const void* p) {
    uint32_t a;
    asm("{ .reg .u64 t; cvta.to.shared.u64 t, %1; cvt.u32.u64 %0, t; }" : "=r"(a) : "l"(p));
    return a;
}
__device__ __forceinline__ void ldm_x4(uint32_t& r0, uint32_t& r1, uint32_t& r2, uint32_t& r3, uint32_t addr) {
    asm volatile("ldmatrix.sync.aligned.m8n8.x4.shared.b16 {%0,%1,%2,%3}, [%4];"
                 : "=r"(r0), "=r"(r1), "=r"(r2), "=r"(r3) : "r"(addr));
}
__device__ __forceinline__ void ldm_x2(uint32_t& r0, uint32_t& r1, uint32_t addr) {
    asm volatile("ldmatrix.sync.aligned.m8n8.x2.shared.b16 {%0,%1}, [%2];"
                 : "=r"(r0), "=r"(r1) : "r"(addr));
}
__device__ __forceinline__ void mma16816(float* c, const uint32_t* a, uint32_t b0, uint32_t b1) {
    asm volatile("mma.sync.aligned.m16n8k16.row.col.f32.f16.f16.f32 "
                 "{%0,%1,%2,%3}, {%4,%5,%6,%7}, {%8,%9}, {%0,%1,%2,%3};"
                 : "+f"(c[0]), "+f"(c[1]), "+f"(c[2]), "+f"(c[3])
                 : "r"(a[0]), "r"(a[1]), "r"(a[2]), "r"(a[3]), "r"(b0), "r"(b1));
}

// ---------------- preprocess: planes -> fp16 [3][300][300][40] ----------------
__global__ void transpose_planes_kernel(const float* __restrict__ planes) {
    int b = blockIdx.x;
    int xt = b % 10;
    int rest = b / 10;
    int y = rest % GRID_D;
    int p = rest / GRID_D;
    int x0 = xt * 32;
    __shared__ float tile[NCOMP][33];
    for (int idx = threadIdx.x; idx < NCOMP * 32; idx += blockDim.x) {
        int c = idx >> 5, xx = idx & 31;
        if (x0 + xx < GRID_D)
            tile[c][xx] = planes[((p * NCOMP + c) * GRID_D + y) * GRID_D + x0 + xx];
    }
    __syncthreads();
    for (int idx = threadIdx.x; idx < 32 * NCOMP; idx += blockDim.x) {
        int xx = idx / NCOMP, c = idx % NCOMP;
        if (x0 + xx < GRID_D)
            g_planesTh[((size_t)(p * GRID_D + y) * GRID_D + (x0 + xx)) * CPAD + c] =
                __float2half_rn(tile[c][xx]);
    }
}

// ---------------- preprocess: fp16 weights (permuted, bias-folded) + fp16 lines ----------------
// A channel order: k 0..107 = feat (orig mlp_in 21..128), k 108..128 = embed (orig 0..20),
//                  k 129 = bias row (A=1, W1=b1), k 130..143 = 0.
__global__ void prep_small_kernel(const float* __restrict__ w1, const float* __restrict__ b1,
                                  const float* __restrict__ w2,
                                  const float* __restrict__ lines) {
    int i = blockIdx.x * blockDim.x + threadIdx.x;
    const int W1N = SDF_DIM * K1;        // 36864
    const int W2N = N2P * K2;            // 34816
    const int LNT = 3 * GRID_D * CPAD;   // 36000
    if (i < W1N) {
        int j = i / K1, k = i % K1;
        float v = 0.0f;
        if (k < 108)       v = w1[j * OUT_CH + 21 + k];
        else if (k < 129)  v = w1[j * OUT_CH + (k - 108)];
        else if (k == 129) v = b1[j];
        g_w1h[i] = __float2half_rn(v);
    } else if (i < W1N + W2N) {
        int t = i - W1N;
        int o = t / K2, j = t % K2;
        g_w2h[t] = __float2half_rn((o < OUT_CH) ? w2[o * SDF_DIM + j] : 0.0f);
    } else if (i < W1N + W2N + LNT) {
        int t = i - W1N - W2N;
        int c = t % CPAD;
        int z = (t / CPAD) % GRID_D;
        int p = t / (CPAD * GRID_D);
        g_linesTh[t] = __float2half_rn((c < NCOMP) ? lines[(p * NCOMP + c) * GRID_D + z] : 0.0f);
    }
}

// ---------------- activation: softplus(100u)/100 ----------------
__device__ __forceinline__ float actf(float u) {
    float t = 100.0f * u;
    return (fmaxf(t, 0.0f) + __logf(1.0f + __expf(-fabsf(t)))) * 0.01f;
}

union V10 { uint4 u[10]; __half2 h[40]; };

// ---------------- persistent fused main kernel ----------------
__global__ __launch_bounds__(NTHR)
void tensosdf_main_kernel(const float* __restrict__ xyz,
                          const float* __restrict__ b2,
                          float* __restrict__ out) {
    extern __shared__ char smem[];
    const uint32_t su = smem_to_u32(smem);
    const int tid  = threadIdx.x;
    const int wid  = tid >> 5;
    const int lane = tid & 31;
    float* b2s = (float*)(smem + SM_B2);

    // ---- stage weights into smem once per CTA ----
    {
        __half* sW1 = (__half*)(smem + SM_W1);
        __half* sW2 = (__half*)(smem + SM_W2);
        for (int i = tid; i < SDF_DIM * K1; i += NTHR) {
            int j = i / K1, k = i % K1;
            sW1[j * AP + k] = g_w1h[i];
        }
        for (int i = tid; i < N2P * K2; i += NTHR) {
            int o = i >> 8, j = i & 255;
            sW2[o * HP + j] = g_w2h[i];
        }
        if (tid < N2P) b2s[tid] = (tid < OUT_CH) ? b2[tid] : 0.0f;
    }
    __syncthreads();

    const int mw = wid >> 2;   // 0..2 : 32-point m-slab
    const int nw = wid & 3;    // 0..3 : n-slab
    const int g  = lane >> 2;  // mma C-frag row group
    const int tq = lane & 3;   // mma C-frag col pair

    const int a_row  = (lane & 15);
    const int a_koff = (lane >> 4) * 8;          // halves
    const int b_row  = (lane & 7);
    const int b_koff = ((lane >> 3) & 1) * 8;    // halves

    for (int tile = blockIdx.x; tile < NTILES; tile += gridDim.x) {
        const int pt0 = tile * TILE_M;

        // ======== Phase A: gather + embed -> A smem (fp16) ========
        if (tid < 288) {
            int point = tid / 3;
            int p     = tid - point * 3;
            int gp = pt0 + point;
            if (gp >= NPTS) gp = NPTS - 1;
            float x = xyz[gp * 3 + 0];
            float y = xyz[gp * 3 + 1];
            float z = xyz[gp * 3 + 2];
            float sx, sy, sz;
            if (p == 0)      { sx = x; sy = y; sz = z; }
            else if (p == 1) { sx = x; sy = z; sz = y; }
            else             { sx = y; sy = z; sz = x; }
            const float HALF = 0.5f * (GRID_D - 1);
            float fx = (sx + 1.0f) * HALF;
            float fy = (sy + 1.0f) * HALF;
            float fz = (sz + 1.0f) * HALF;
            int x0 = min(max((int)floorf(fx), 0), GRID_D - 2);
            int y0 = min(max((int)floorf(fy), 0), GRID_D - 2);
            int z0 = min(max((int)floorf(fz), 0), GRID_D - 2);
            float tx = fx - (float)x0;
            float ty = fy - (float)y0;
            float tz = fz - (float)z0;
            float w00 = (1.0f - tx) * (1.0f - ty);
            float w01 = tx * (1.0f - ty);
            float w10 = (1.0f - tx) * ty;
            float w11 = tx * ty;

            const uint4* r0p = (const uint4*)(g_planesTh + ((size_t)(p * GRID_D + y0) * GRID_D + x0) * CPAD);
            const uint4* lp  = (const uint4*)(g_linesTh + (size_t)(p * GRID_D + z0) * CPAD);
            V10 R0, R1, RL;
            #pragma unroll
            for (int i = 0; i < 10; i++) R0.u[i] = r0p[i];
            #pragma unroll
            for (int i = 0; i < 10; i++) R1.u[i] = r0p[GRID_D * CPAD / 8 + i];
            #pragma unroll
            for (int i = 0; i < 10; i++) RL.u[i] = lp[i];

            char* dst = smem + SM_A + point * (AP * 2) + p * NCOMP * 2;
            #pragma unroll
            for (int cc = 0; cc < 9; cc++) {
                uint2 pk;
                #pragma unroll
                for (int half_q = 0; half_q < 2; half_q++) {
                    int hi2 = 2 * cc + half_q;
                    float2 v00 = __half22float2(R0.h[hi2]);
                    float2 v01 = __half22float2(R0.h[20 + hi2]);
                    float2 v10 = __half22float2(R1.h[hi2]);
                    float2 v11 = __half22float2(R1.h[20 + hi2]);
                    float2 l0  = __half22float2(RL.h[hi2]);
                    float2 l1  = __half22float2(RL.h[20 + hi2]);
                    float ra = (v00.x * w00 + v01.x * w01 + v10.x * w10 + v11.x * w11)
                             * (l0.x + (l1.x - l0.x) * tz);
                    float rb = (v00.y * w00 + v01.y * w01 + v10.y * w10 + v11.y * w11)
                             * (l0.y + (l1.y - l0.y) * tz);
                    __half2 hh = __floats2half2_rn(ra, rb);
                    if (half_q == 0) pk.x = *(uint32_t*)&hh; else pk.y = *(uint32_t*)&hh;
                }
                *(uint2*)(dst + cc * 8) = pk;
            }
        } else {
            int point = tid - 288;
            int gp = pt0 + point;
            if (gp >= NPTS) gp = NPTS - 1;
            float vx = xyz[gp * 3 + 0];
            float vy = xyz[gp * 3 + 1];
            float vz = xyz[gp * 3 + 2];
            float e[22];
            e[0] = vx; e[1] = vy; e[2] = vz;
            #pragma unroll
            for (int d = 0; d < 3; d++) {
                float v = (d == 0) ? vx : (d == 1) ? vy : vz;
                #pragma unroll
                for (int f = 0; f < 3; f++) {
                    float s, c;
                    sincosf(v * (float)(1 << f), &s, &c);
                    e[3 + d * 3 + f]  = s;
                    e[12 + d * 3 + f] = c;
                }
            }
            e[21] = 1.0f;  // bias row at k=129
            char* dst = smem + SM_A + point * (AP * 2) + 108 * 2;
            #pragma unroll
            for (int i = 0; i < 18; i++) {
                int k0 = 108 + 2 * i;
                float lo = (k0 <= 129) ? e[k0 - 108] : 0.0f;
                float hi = (k0 + 1 <= 129) ? e[k0 + 1 - 108] : 0.0f;
                __half2 h = __floats2half2_rn(lo, hi);
                *(uint32_t*)(dst + i * 4) = *(uint32_t*)&h;
            }
        }
        __syncthreads();   // S1: A ready (also orders H(t) reads vs H(t+1) writes)

        // ======== GEMM1: H = act(A @ W1^T), 4 acc chains/warp (t x k-parity) ========
        {
            uint32_t Af[2][9][4];
            const uint32_t a_base = su + SM_A + (uint32_t)(mw * 32 + a_row) * (AP * 2) + (uint32_t)a_koff * 2;
            #pragma unroll
            for (int t = 0; t < 2; t++)
                #pragma unroll
                for (int s = 0; s < 9; s++)
                    ldm_x4(Af[t][s][0], Af[t][s][1], Af[t][s][2], Af[t][s][3],
                           a_base + (uint32_t)t * 16 * (AP * 2) + (uint32_t)s * 32);

            const uint32_t b_base = su + SM_W1 + (uint32_t)(nw * 64 + b_row) * (AP * 2) + (uint32_t)b_koff * 2;
            #pragma unroll
            for (int jt = 0; jt < 8; jt++) {
                float acc[2][2][4] = {{{0,0,0,0},{0,0,0,0}},{{0,0,0,0},{0,0,0,0}}};  // [t][parity][frag]
                #pragma unroll
                for (int s = 0; s < 9; s++) {
                    uint32_t b0, b1v;
                    ldm_x2(b0, b1v, b_base + (uint32_t)jt * 8 * (AP * 2) + (uint32_t)s * 32);
                    mma16816(acc[0][s & 1], Af[0][s], b0, b1v);
                    mma16816(acc[1][s & 1], Af[1][s], b0, b1v);
                }
                #pragma unroll
                for (int t = 0; t < 2; t++) {
                    float c0 = acc[t][0][0] + acc[t][1][0];
                    float c1 = acc[t][0][1] + acc[t][1][1];
                    float c2 = acc[t][0][2] + acc[t][1][2];
                    float c3 = acc[t][0][3] + acc[t][1][3];
                    __half2 hlo = __floats2half2_rn(actf(c0), actf(c1));
                    __half2 hhi = __floats2half2_rn(actf(c2), actf(c3));
                    char* hp0 = smem + SM_H + (mw * 32 + t * 16 + g) * (HP * 2)
                              + (nw * 64 + jt * 8 + tq * 2) * 2;
                    *(uint32_t*)hp0 = *(uint32_t*)&hlo;
                    *(uint32_t*)(hp0 + 8 * (HP * 2)) = *(uint32_t*)&hhi;
                }
            }
        }
        __syncthreads();   // S2: H ready (also ends all A reads before next gather)

        // ======== GEMM2: out = H @ W2^T + b2, 2 acc chains per (t,j) ========
        {
            const uint32_t h_base = su + SM_H + (uint32_t)(mw * 32 + a_row) * (HP * 2) + (uint32_t)a_koff * 2;
            const uint32_t w2_base = su + SM_W2 + (uint32_t)b_row * (HP * 2) + (uint32_t)b_koff * 2;
            #pragma unroll 1
            for (int t = 0; t < 2; t++) {
                uint32_t Hf[16][4];
                #pragma unroll
                for (int s = 0; s < 16; s++)
                    ldm_x4(Hf[s][0], Hf[s][1], Hf[s][2], Hf[s][3],
                           h_base + (uint32_t)t * 16 * (HP * 2) + (uint32_t)s * 32);
                #pragma unroll 1
                for (int j5 = 0; j5 < 5; j5++) {
                    const int jt = nw + j5 * 4;
                    if (jt >= 17) break;
                    const int o_base = jt * 8;
                    float aE[4] = {0, 0, 0, 0};
                    float aO[4] = {0, 0, 0, 0};
                    const uint32_t wb = w2_base + (uint32_t)o_base * (HP * 2);
                    #pragma unroll
                    for (int s = 0; s < 16; s++) {
                        uint32_t b0, b1v;
                        ldm_x2(b0, b1v, wb + (uint32_t)s * 32);
                        mma16816((s & 1) ? aO : aE, Hf[s], b0, b1v);
                    }
                    const int oc = o_base + tq * 2;
                    const int pr = pt0 + mw * 32 + t * 16 + g;
                    if (pr < NPTS && oc < OUT_CH) {
                        out[(size_t)pr * OUT_CH + oc] = aE[0] + aO[0] + b2s[oc];
                        if (oc + 1 < OUT_CH)
                            out[(size_t)pr * OUT_CH + oc + 1] = aE[1] + aO[1] + b2s[oc + 1];
                    }
                    if (pr + 8 < NPTS && oc < OUT_CH) {
                        out[(size_t)(pr + 8) * OUT_CH + oc] = aE[2] + aO[2] + b2s[oc];
                        if (oc + 1 < OUT_CH)
                            out[(size_t)(pr + 8) * OUT_CH + oc + 1] = aE[3] + aO[3] + b2s[oc + 1];
                    }
                }
            }
        }
        // no 3rd barrier: next S1 provides the H(t)-read / H(t+1)-write ordering,
        // and gather(t+1) only writes A, which no warp touches after S2.
    }
}

// ---------------- launch ----------------
extern "C" void kernel_launch(void* const* d_in, const int* in_sizes, int n_in,
                              void* d_out, int out_size) {
    const float* xyz    = (const float*)d_in[0];
    const float* planes = (const float*)d_in[1];
    const float* lines  = (const float*)d_in[2];
    const float* w1     = (const float*)d_in[3];
    const float* b1     = (const float*)d_in[4];
    const float* w2     = (const float*)d_in[5];
    const float* b2     = (const float*)d_in[6];
    float* out = (float*)d_out;

    int nsm = 148;
    cudaDeviceGetAttribute(&nsm, cudaDevAttrMultiProcessorCount, 0);

    cudaFuncSetAttribute(tensosdf_main_kernel,
                         cudaFuncAttributeMaxDynamicSharedMemorySize, SM_TOTAL);

    transpose_planes_kernel<<<3 * GRID_D * 10, 256>>>(planes);

    const int prep_total = SDF_DIM * K1 + N2P * K2 + 3 * GRID_D * CPAD;
    prep_small_kernel<<<(prep_total + 255) / 256, 256>>>(w1, b1, w2, lines);

    tensosdf_main_kernel<<<nsm, NTHR, SM_TOTAL>>>(xyz, b2, out);
}

// round 12
// speedup vs baseline: 10.0266x; 1.3414x over previous
#include <cuda_runtime.h>
#include <cuda_fp16.h>
#include <math.h>
#include <stdint.h>

// ---------------- problem constants ----------------
#define NPTS    524288
#define GRID_D  300
#define NCOMP   36
#define CPAD    64        // channel dim padded to 64 halves = 128B (one aligned line per corner)
#define SDF_DIM 256
#define OUT_CH  129
#define K1      144       // GEMM1 K (129 used + pad), 9 k-steps
#define AP      152       // A / W1 smem pitch in halves (304B -> conflict-free ldmatrix)
#define N2P     136       // GEMM2 N padded (129 used), 17 n-tiles of 8
#define K2      256       // GEMM2 K, 16 k-steps
#define HP      264       // H / W2 smem pitch in halves (528B -> conflict-free)
#define TILE_M  96
#define NTILES  ((NPTS + TILE_M - 1) / TILE_M)   // 5462 (last tile partial: 32 pts)
#define NTHR    384

// ---------------- smem layout (bytes) ----------------
#define SM_A   0
#define SM_H   (SM_A + TILE_M * AP * 2)       // 29184
#define SM_W1  (SM_H + TILE_M * HP * 2)       // +50688 = 79872
#define SM_W2  (SM_W1 + SDF_DIM * AP * 2)     // +77824 = 157696
#define SM_B2  (SM_W2 + N2P * HP * 2)         // +71808 = 229504
#define SM_TOTAL (SM_B2 + N2P * 4)            // 230048

// ---------------- scratch globals ----------------
__device__ __align__(16) __half g_planesTh[3 * GRID_D * GRID_D * CPAD]; // [p][y][x][c64] fp16 (c>=36 zero)
__device__ __align__(16) __half g_linesTh[3 * GRID_D * CPAD];           // [p][z][c64] fp16 (c>=36 zero)
__device__ __align__(16) __half g_w1h[SDF_DIM * K1];                    // [j][k] (permuted, bias row k=129)
__device__ __align__(16) __half g_w2h[N2P * K2];                        // [o][j] (rows >=129 zero)

// ---------------- PTX helpers (sm_80-era, compile on plain sm_103) ----------------
__device__ __forceinline__ uint32_t smem_to_u32(const void* p) {
    uint32_t a;
    asm("{ .reg .u64 t; cvta.to.shared.u64 t, %1; cvt.u32.u64 %0, t; }" : "=r"(a) : "l"(p));
    return a;
}
__device__ __forceinline__ void ldm_x4(uint32_t& r0, uint32_t& r1, uint32_t& r2, uint32_t& r3, uint32_t addr) {
    asm volatile("ldmatrix.sync.aligned.m8n8.x4.shared.b16 {%0,%1,%2,%3}, [%4];"
                 : "=r"(r0), "=r"(r1), "=r"(r2), "=r"(r3) : "r"(addr));
}
__device__ __forceinline__ void ldm_x2(uint32_t& r0, uint32_t& r1, uint32_t addr) {
    asm volatile("ldmatrix.sync.aligned.m8n8.x2.shared.b16 {%0,%1}, [%2];"
                 : "=r"(r0), "=r"(r1) : "r"(addr));
}
__device__ __forceinline__ void mma16816(float* c, const uint32_t* a, uint32_t b0, uint32_t b1) {
    asm volatile("mma.sync.aligned.m16n8k16.row.col.f32.f16.f16.f32 "
                 "{%0,%1,%2,%3}, {%4,%5,%6,%7}, {%8,%9}, {%0,%1,%2,%3};"
                 : "+f"(c[0]), "+f"(c[1]), "+f"(c[2]), "+f"(c[3])
                 : "r"(a[0]), "r"(a[1]), "r"(a[2]), "r"(a[3]), "r"(b0), "r"(b1));
}

// ---------------- preprocess: planes -> fp16 [3][300][300][64] (pad ch zeroed) ----------------
__global__ void transpose_planes_kernel(const float* __restrict__ planes) {
    int b = blockIdx.x;
    int xt = b % 10;
    int rest = b / 10;
    int y = rest % GRID_D;
    int p = rest / GRID_D;
    int x0 = xt * 32;
    __shared__ float tile[NCOMP][33];
    for (int idx = threadIdx.x; idx < NCOMP * 32; idx += blockDim.x) {
        int c = idx >> 5, xx = idx & 31;
        if (x0 + xx < GRID_D)
            tile[c][xx] = planes[((p * NCOMP + c) * GRID_D + y) * GRID_D + x0 + xx];
    }
    __syncthreads();
    for (int idx = threadIdx.x; idx < 32 * CPAD; idx += blockDim.x) {
        int xx = idx / CPAD, c = idx % CPAD;
        if (x0 + xx < GRID_D)
            g_planesTh[((size_t)(p * GRID_D + y) * GRID_D + (x0 + xx)) * CPAD + c] =
                __float2half_rn((c < NCOMP) ? tile[c][xx] : 0.0f);
    }
}

// ---------------- preprocess: fp16 weights (permuted, bias-folded) + fp16 lines ----------------
// A channel order: k 0..107 = feat (orig mlp_in 21..128), k 108..128 = embed (orig 0..20),
//                  k 129 = bias row (A=1, W1=b1), k 130..143 = 0.
__global__ void prep_small_kernel(const float* __restrict__ w1, const float* __restrict__ b1,
                                  const float* __restrict__ w2,
                                  const float* __restrict__ lines) {
    int i = blockIdx.x * blockDim.x + threadIdx.x;
    const int W1N = SDF_DIM * K1;        // 36864
    const int W2N = N2P * K2;            // 34816
    const int LNT = 3 * GRID_D * CPAD;   // 57600
    if (i < W1N) {
        int j = i / K1, k = i % K1;
        float v = 0.0f;
        if (k < 108)       v = w1[j * OUT_CH + 21 + k];
        else if (k < 129)  v = w1[j * OUT_CH + (k - 108)];
        else if (k == 129) v = b1[j];
        g_w1h[i] = __float2half_rn(v);
    } else if (i < W1N + W2N) {
        int t = i - W1N;
        int o = t / K2, j = t % K2;
        g_w2h[t] = __float2half_rn((o < OUT_CH) ? w2[o * SDF_DIM + j] : 0.0f);
    } else if (i < W1N + W2N + LNT) {
        int t = i - W1N - W2N;
        int c = t % CPAD;
        int z = (t / CPAD) % GRID_D;
        int p = t / (CPAD * GRID_D);
        g_linesTh[t] = __float2half_rn((c < NCOMP) ? lines[(p * NCOMP + c) * GRID_D + z] : 0.0f);
    }
}

// ---------------- activation: softplus(100u)/100 ----------------
__device__ __forceinline__ float actf(float u) {
    float t = 100.0f * u;
    return (fmaxf(t, 0.0f) + __logf(1.0f + __expf(-fabsf(t)))) * 0.01f;
}

union U4H { uint4 u; __half2 h[4]; };

// ---------------- persistent fused main kernel ----------------
__global__ __launch_bounds__(NTHR)
void tensosdf_main_kernel(const float* __restrict__ xyz,
                          const float* __restrict__ b2,
                          float* __restrict__ out) {
    extern __shared__ char smem[];
    const uint32_t su = smem_to_u32(smem);
    const int tid  = threadIdx.x;
    const int wid  = tid >> 5;
    const int lane = tid & 31;
    float* b2s = (float*)(smem + SM_B2);

    // ---- stage weights into smem once per CTA ----
    {
        __half* sW1 = (__half*)(smem + SM_W1);
        __half* sW2 = (__half*)(smem + SM_W2);
        for (int i = tid; i < SDF_DIM * K1; i += NTHR) {
            int j = i / K1, k = i % K1;
            sW1[j * AP + k] = g_w1h[i];
        }
        for (int i = tid; i < N2P * K2; i += NTHR) {
            int o = i >> 8, j = i & 255;
            sW2[o * HP + j] = g_w2h[i];
        }
        if (tid < N2P) b2s[tid] = (tid < OUT_CH) ? b2[tid] : 0.0f;
    }
    __syncthreads();

    const int mw = wid >> 2;   // 0..2 : 32-point m-slab
    const int nw = wid & 3;    // 0..3 : n-slab
    const int g  = lane >> 2;  // mma C-frag row group
    const int tq = lane & 3;   // mma C-frag col pair

    const int a_row  = (lane & 15);
    const int a_koff = (lane >> 4) * 8;          // halves
    const int b_row  = (lane & 7);
    const int b_koff = ((lane >> 3) & 1) * 8;    // halves

    const int lc = lane & 7;   // 8-channel chunk within corner line
    const int kt = lane >> 3;  // task slot within round (0..3)

    for (int tile = blockIdx.x; tile < NTILES; tile += gridDim.x) {
        const int pt0 = tile * TILE_M;

        // ======== Phase A: cooperative gather (all 12 warps) + embed ========
        // warp handles 24 (point,plane) tasks in 6 rounds of 4; 8 lanes per task,
        // lanes 0..4 of each group active (channels lc*8 .. lc*8+8, 36 used + pad)
        #pragma unroll
        for (int r = 0; r < 6; r++) {
            const int T = wid * 24 + r * 4 + kt;
            const int point = T / 3;
            const int pl    = T - point * 3;
            if (lc < 5) {
                int gp = pt0 + point;
                if (gp >= NPTS) gp = NPTS - 1;
                float x = xyz[gp * 3 + 0];
                float y = xyz[gp * 3 + 1];
                float z = xyz[gp * 3 + 2];
                float sx, sy, sz;
                if (pl == 0)      { sx = x; sy = y; sz = z; }
                else if (pl == 1) { sx = x; sy = z; sz = y; }
                else              { sx = y; sy = z; sz = x; }
                const float HALF = 0.5f * (GRID_D - 1);
                float fx = (sx + 1.0f) * HALF;
                float fy = (sy + 1.0f) * HALF;
                float fz = (sz + 1.0f) * HALF;
                int x0 = min(max((int)floorf(fx), 0), GRID_D - 2);
                int y0 = min(max((int)floorf(fy), 0), GRID_D - 2);
                int z0 = min(max((int)floorf(fz), 0), GRID_D - 2);
                float tx = fx - (float)x0;
                float ty = fy - (float)y0;
                float tz = fz - (float)z0;
                float w00 = (1.0f - tx) * (1.0f - ty);
                float w01 = tx * (1.0f - ty);
                float w10 = (1.0f - tx) * ty;
                float w11 = tx * ty;

                // one aligned 128B line per corner; this lane takes halves [lc*8, lc*8+8)
                const __half* P = g_planesTh + ((size_t)(pl * GRID_D + y0) * GRID_D + x0) * CPAD + lc * 8;
                const __half* L = g_linesTh + ((size_t)(pl * GRID_D + z0)) * CPAD + lc * 8;
                U4H v00, v01, v10, v11, l0v, l1v;
                v00.u = *(const uint4*)(P);
                v01.u = *(const uint4*)(P + CPAD);
                v10.u = *(const uint4*)(P + GRID_D * CPAD);
                v11.u = *(const uint4*)(P + GRID_D * CPAD + CPAD);
                l0v.u = *(const uint4*)(L);
                l1v.u = *(const uint4*)(L + CPAD);

                uint32_t res[4];
                #pragma unroll
                for (int i = 0; i < 4; i++) {
                    float2 a00 = __half22float2(v00.h[i]);
                    float2 a01 = __half22float2(v01.h[i]);
                    float2 a10 = __half22float2(v10.h[i]);
                    float2 a11 = __half22float2(v11.h[i]);
                    float2 b0  = __half22float2(l0v.h[i]);
                    float2 b1  = __half22float2(l1v.h[i]);
                    float ra = (a00.x * w00 + a01.x * w01 + a10.x * w10 + a11.x * w11)
                             * (b0.x + (b1.x - b0.x) * tz);
                    float rb = (a00.y * w00 + a01.y * w01 + a10.y * w10 + a11.y * w11)
                             * (b0.y + (b1.y - b0.y) * tz);
                    __half2 hh = __floats2half2_rn(ra, rb);
                    res[i] = *(uint32_t*)&hh;
                }
                char* dst = smem + SM_A + point * (AP * 2) + (pl * NCOMP + lc * 8) * 2;
                uint2 lo; lo.x = res[0]; lo.y = res[1];
                *(uint2*)dst = lo;
                if (lc < 4) {           // lc==4 owns ch 32..35 only (8B); 36..39 are A-pad? no: ch36.. is next plane's cols
                    uint2 hi; hi.x = res[2]; hi.y = res[3];
                    *(uint2*)(dst + 8) = hi;
                }
            }
        }
        // embed: one point per thread (tid < 96)
        if (tid < TILE_M) {
            int gp = pt0 + tid;
            if (gp >= NPTS) gp = NPTS - 1;
            float vx = xyz[gp * 3 + 0];
            float vy = xyz[gp * 3 + 1];
            float vz = xyz[gp * 3 + 2];
            float e[22];
            e[0] = vx; e[1] = vy; e[2] = vz;
            #pragma unroll
            for (int d = 0; d < 3; d++) {
                float v = (d == 0) ? vx : (d == 1) ? vy : vz;
                #pragma unroll
                for (int f = 0; f < 3; f++) {
                    float s, c;
                    sincosf(v * (float)(1 << f), &s, &c);
                    e[3 + d * 3 + f]  = s;
                    e[12 + d * 3 + f] = c;
                }
            }
            e[21] = 1.0f;  // bias row at k=129
            char* dst = smem + SM_A + tid * (AP * 2) + 108 * 2;
            #pragma unroll
            for (int i = 0; i < 18; i++) {
                int k0 = 108 + 2 * i;
                float lo = (k0 <= 129) ? e[k0 - 108] : 0.0f;
                float hi = (k0 + 1 <= 129) ? e[k0 + 1 - 108] : 0.0f;
                __half2 h = __floats2half2_rn(lo, hi);
                *(uint32_t*)(dst + i * 4) = *(uint32_t*)&h;
            }
        }
        __syncthreads();   // S1: A ready (also orders H(t) reads vs H(t+1) writes)

        // ======== GEMM1: H = act(A @ W1^T), 4 acc chains/warp (t x k-parity) ========
        {
            uint32_t Af[2][9][4];
            const uint32_t a_base = su + SM_A + (uint32_t)(mw * 32 + a_row) * (AP * 2) + (uint32_t)a_koff * 2;
            #pragma unroll
            for (int t = 0; t < 2; t++)
                #pragma unroll
                for (int s = 0; s < 9; s++)
                    ldm_x4(Af[t][s][0], Af[t][s][1], Af[t][s][2], Af[t][s][3],
                           a_base + (uint32_t)t * 16 * (AP * 2) + (uint32_t)s * 32);

            const uint32_t b_base = su + SM_W1 + (uint32_t)(nw * 64 + b_row) * (AP * 2) + (uint32_t)b_koff * 2;
            #pragma unroll
            for (int jt = 0; jt < 8; jt++) {
                float acc[2][2][4] = {{{0,0,0,0},{0,0,0,0}},{{0,0,0,0},{0,0,0,0}}};
                #pragma unroll
                for (int s = 0; s < 9; s++) {
                    uint32_t b0, b1v;
                    ldm_x2(b0, b1v, b_base + (uint32_t)jt * 8 * (AP * 2) + (uint32_t)s * 32);
                    mma16816(acc[0][s & 1], Af[0][s], b0, b1v);
                    mma16816(acc[1][s & 1], Af[1][s], b0, b1v);
                }
                #pragma unroll
                for (int t = 0; t < 2; t++) {
                    float c0 = acc[t][0][0] + acc[t][1][0];
                    float c1 = acc[t][0][1] + acc[t][1][1];
                    float c2 = acc[t][0][2] + acc[t][1][2];
                    float c3 = acc[t][0][3] + acc[t][1][3];
                    __half2 hlo = __floats2half2_rn(actf(c0), actf(c1));
                    __half2 hhi = __floats2half2_rn(actf(c2), actf(c3));
                    char* hp0 = smem + SM_H + (mw * 32 + t * 16 + g) * (HP * 2)
                              + (nw * 64 + jt * 8 + tq * 2) * 2;
                    *(uint32_t*)hp0 = *(uint32_t*)&hlo;
                    *(uint32_t*)(hp0 + 8 * (HP * 2)) = *(uint32_t*)&hhi;
                }
            }
        }
        __syncthreads();   // S2: H ready (also ends all A reads before next gather)

        // ======== GEMM2: out = H @ W2^T + b2, 2 acc chains per (t,j) ========
        {
            const uint32_t h_base = su + SM_H + (uint32_t)(mw * 32 + a_row) * (HP * 2) + (uint32_t)a_koff * 2;
            const uint32_t w2_base = su + SM_W2 + (uint32_t)b_row * (HP * 2) + (uint32_t)b_koff * 2;
            #pragma unroll 1
            for (int t = 0; t < 2; t++) {
                uint32_t Hf[16][4];
                #pragma unroll
                for (int s = 0; s < 16; s++)
                    ldm_x4(Hf[s][0], Hf[s][1], Hf[s][2], Hf[s][3],
                           h_base + (uint32_t)t * 16 * (HP * 2) + (uint32_t)s * 32);
                #pragma unroll 1
                for (int j5 = 0; j5 < 5; j5++) {
                    const int jt = nw + j5 * 4;
                    if (jt >= 17) break;
                    const int o_base = jt * 8;
                    float aE[4] = {0, 0, 0, 0};
                    float aO[4] = {0, 0, 0, 0};
                    const uint32_t wb = w2_base + (uint32_t)o_base * (HP * 2);
                    #pragma unroll
                    for (int s = 0; s < 16; s++) {
                        uint32_t b0, b1v;
                        ldm_x2(b0, b1v, wb + (uint32_t)s * 32);
                        mma16816((s & 1) ? aO : aE, Hf[s], b0, b1v);
                    }
                    const int oc = o_base + tq * 2;
                    const int pr = pt0 + mw * 32 + t * 16 + g;
                    if (pr < NPTS && oc < OUT_CH) {
                        out[(size_t)pr * OUT_CH + oc] = aE[0] + aO[0] + b2s[oc];
                        if (oc + 1 < OUT_CH)
                            out[(size_t)pr * OUT_CH + oc + 1] = aE[1] + aO[1] + b2s[oc + 1];
                    }
                    if (pr + 8 < NPTS && oc < OUT_CH) {
                        out[(size_t)(pr + 8) * OUT_CH + oc] = aE[2] + aO[2] + b2s[oc];
                        if (oc + 1 < OUT_CH)
                            out[(size_t)(pr + 8) * OUT_CH + oc + 1] = aE[3] + aO[3] + b2s[oc + 1];
                    }
                }
            }
        }
        // no 3rd barrier: next S1 provides the H(t)-read / H(t+1)-write ordering,
        // and gather(t+1) only writes A, which no warp touches after S2.
    }
}

// ---------------- launch ----------------
extern "C" void kernel_launch(void* const* d_in, const int* in_sizes, int n_in,
                              void* d_out, int out_size) {
    const float* xyz    = (const float*)d_in[0];
    const float* planes = (const float*)d_in[1];
    const float* lines  = (const float*)d_in[2];
    const float* w1     = (const float*)d_in[3];
    const float* b1     = (const float*)d_in[4];
    const float* w2     = (const float*)d_in[5];
    const float* b2     = (const float*)d_in[6];
    float* out = (float*)d_out;

    int nsm = 148;
    cudaDeviceGetAttribute(&nsm, cudaDevAttrMultiProcessorCount, 0);

    cudaFuncSetAttribute(tensosdf_main_kernel,
                         cudaFuncAttributeMaxDynamicSharedMemorySize, SM_TOTAL);

    transpose_planes_kernel<<<3 * GRID_D * 10, 256>>>(planes);

    const int prep_total = SDF_DIM * K1 + N2P * K2 + 3 * GRID_D * CPAD;
    prep_small_kernel<<<(prep_total + 255) / 256, 256>>>(w1, b1, w2, lines);

    tensosdf_main_kernel<<<nsm, NTHR, SM_TOTAL>>>(xyz, b2, out);
}